// round 3
// baseline (speedup 1.0000x reference)
#include <cuda_runtime.h>
#include <math.h>

#define BB 32
#define SS 2048
#define DD 1024
#define HH 1024

// qp scratch: [B, H]
__device__ float g_qp[BB * HH];

// ---------------------------------------------------------------------------
// Kernel 1: query_proj[b,h] = sum_d query[b,d] * W2[d,h]
// grid (B, H/256), 256 threads
// ---------------------------------------------------------------------------
__global__ void __launch_bounds__(256) qp_kernel(const float* __restrict__ query,
                                                 const float* __restrict__ W2) {
    int b = blockIdx.x;
    int h = blockIdx.y * 256 + threadIdx.x;
    __shared__ float qs[DD];
    for (int d = threadIdx.x; d < DD; d += 256) qs[d] = query[b * DD + d];
    __syncthreads();
    float acc0 = 0.f, acc1 = 0.f, acc2 = 0.f, acc3 = 0.f;
    #pragma unroll 4
    for (int d = 0; d < DD; d += 4) {
        acc0 += qs[d + 0] * W2[(size_t)(d + 0) * HH + h];
        acc1 += qs[d + 1] * W2[(size_t)(d + 1) * HH + h];
        acc2 += qs[d + 2] * W2[(size_t)(d + 2) * HH + h];
        acc3 += qs[d + 3] * W2[(size_t)(d + 3) * HH + h];
    }
    g_qp[b * HH + h] = (acc0 + acc1) + (acc2 + acc3);
}

// ---------------------------------------------------------------------------
// Kernel 2: fused scores
//   scores[b,s] = sum_h v[h] * tanh( qp[b,h] + sum_d values[b,s,d]*W1[d,h] )
// Tiled GEMM: block tile 64 rows (s) x 64 cols (h), K-tile 16 (d).
// 256 threads = 16(ty: row groups) x 16(tx: col groups); thread tile 4x4.
// h processed in 16 tiles; tanh*v epilogue folds each h-tile into per-row
// score partials, reduced across tx at the end.
// ---------------------------------------------------------------------------
#define TS 64
#define TH 64
#define TD 16

__global__ void __launch_bounds__(256) scores_kernel(const float* __restrict__ values,
                                                     const float* __restrict__ W1,
                                                     const float* __restrict__ vvec,
                                                     float* __restrict__ scores) {
    __shared__ __align__(16) float As[TD][TS + 4];  // [d][s], transposed values tile
    __shared__ __align__(16) float Bs[TD][TH + 4];  // [d][h]
    __shared__ float qp_sh[TH];
    __shared__ float v_sh[TH];
    __shared__ float red[TS][16];

    const int m0 = blockIdx.x * TS;        // global flattened (b*S+s) row start
    const int b = m0 / SS;                 // S divisible by TS -> block within one b
    const float* vbase = values + (size_t)m0 * DD;

    const int tid = threadIdx.x;
    const int tx = tid & 15;
    const int ty = tid >> 4;

    // global-load indices (reused every tile)
    const int a_s = tid & 63;              // 0..63
    const int a_dg = tid >> 6;             // 0..3  -> d = a_dg*4
    const int b_hq = tid & 15;             // float4 index along h
    const int b_d = tid >> 4;              // 0..15

    float score_acc[4] = {0.f, 0.f, 0.f, 0.f};

    for (int h0 = 0; h0 < HH; h0 += TH) {
        __syncthreads();  // prior epilogue done before overwriting qp_sh/v_sh
        if (tid < TH) {
            qp_sh[tid] = g_qp[b * HH + h0 + tid];
            v_sh[tid] = vvec[h0 + tid];
        }

        float kp[4][4];
        #pragma unroll
        for (int i = 0; i < 4; i++)
            #pragma unroll
            for (int j = 0; j < 4; j++) kp[i][j] = 0.f;

        for (int d0 = 0; d0 < DD; d0 += TD) {
            __syncthreads();
            // A tile: values[m0 + s][d0 + 4*a_dg .. +3] -> As[d][s] (transpose)
            {
                float4 va = *reinterpret_cast<const float4*>(
                    vbase + (size_t)a_s * DD + d0 + a_dg * 4);
                As[a_dg * 4 + 0][a_s] = va.x;
                As[a_dg * 4 + 1][a_s] = va.y;
                As[a_dg * 4 + 2][a_s] = va.z;
                As[a_dg * 4 + 3][a_s] = va.w;
            }
            // B tile: W1[d0 + b_d][h0 + 4*b_hq .. +3]
            {
                float4 wb = *reinterpret_cast<const float4*>(
                    W1 + (size_t)(d0 + b_d) * HH + h0 + b_hq * 4);
                *reinterpret_cast<float4*>(&Bs[b_d][b_hq * 4]) = wb;
            }
            __syncthreads();
            #pragma unroll
            for (int d = 0; d < TD; d++) {
                float4 af = *reinterpret_cast<const float4*>(&As[d][ty * 4]);
                float4 bf = *reinterpret_cast<const float4*>(&Bs[d][tx * 4]);
                float a[4] = {af.x, af.y, af.z, af.w};
                float bb[4] = {bf.x, bf.y, bf.z, bf.w};
                #pragma unroll
                for (int i = 0; i < 4; i++)
                    #pragma unroll
                    for (int j = 0; j < 4; j++) kp[i][j] += a[i] * bb[j];
            }
        }

        // epilogue: fold this h-tile into score partials
        #pragma unroll
        for (int i = 0; i < 4; i++) {
            float part = 0.f;
            #pragma unroll
            for (int j = 0; j < 4; j++) {
                int hh = tx * 4 + j;
                float e = tanhf(kp[i][j] + qp_sh[hh]);
                part += v_sh[hh] * e;
            }
            score_acc[i] += part;
        }
    }

    // reduce score partials across the 16 tx threads of each row
    #pragma unroll
    for (int i = 0; i < 4; i++) red[ty * 4 + i][tx] = score_acc[i];
    __syncthreads();
    if (tid < TS) {
        float s = 0.f;
        #pragma unroll
        for (int t = 0; t < 16; t++) s += red[tid][t];
        scores[m0 + tid] = s;
    }
}

// ---------------------------------------------------------------------------
// Kernel 3: in-place softmax over S per batch row
// ---------------------------------------------------------------------------
__global__ void __launch_bounds__(256) softmax_kernel(float* __restrict__ w) {
    int b = blockIdx.x;
    float* row = w + (size_t)b * SS;
    __shared__ float sdata[256];
    int tid = threadIdx.x;

    float m = -INFINITY;
    for (int s = tid; s < SS; s += 256) m = fmaxf(m, row[s]);
    sdata[tid] = m;
    __syncthreads();
    for (int o = 128; o > 0; o >>= 1) {
        if (tid < o) sdata[tid] = fmaxf(sdata[tid], sdata[tid + o]);
        __syncthreads();
    }
    m = sdata[0];
    __syncthreads();

    float sum = 0.f;
    for (int s = tid; s < SS; s += 256) {
        float e = expf(row[s] - m);
        row[s] = e;
        sum += e;
    }
    sdata[tid] = sum;
    __syncthreads();
    for (int o = 128; o > 0; o >>= 1) {
        if (tid < o) sdata[tid] += sdata[tid + o];
        __syncthreads();
    }
    float inv = 1.f / sdata[0];
    for (int s = tid; s < SS; s += 256) row[s] *= inv;
}

// ---------------------------------------------------------------------------
// Kernel 4: context[b,d] = sum_s w[b,s] * values[b,s,d]
// grid (B, D/256), 256 threads
// ---------------------------------------------------------------------------
__global__ void __launch_bounds__(256) context_kernel(const float* __restrict__ values,
                                                      const float* __restrict__ w,
                                                      float* __restrict__ ctx) {
    int b = blockIdx.x;
    int d = blockIdx.y * 256 + threadIdx.x;
    __shared__ float ws[SS];
    for (int s = threadIdx.x; s < SS; s += 256) ws[s] = w[(size_t)b * SS + s];
    __syncthreads();
    const float* vb = values + (size_t)b * SS * DD + d;
    float a0 = 0.f, a1 = 0.f, a2 = 0.f, a3 = 0.f;
    #pragma unroll 2
    for (int s = 0; s < SS; s += 4) {
        a0 += ws[s + 0] * vb[(size_t)(s + 0) * DD];
        a1 += ws[s + 1] * vb[(size_t)(s + 1) * DD];
        a2 += ws[s + 2] * vb[(size_t)(s + 2) * DD];
        a3 += ws[s + 3] * vb[(size_t)(s + 3) * DD];
    }
    ctx[b * DD + d] = (a0 + a1) + (a2 + a3);
}

// ---------------------------------------------------------------------------
// launch: inputs in metadata order: query, values, W1, W2, v
// output: [context (B*D) | attention_weights (B*S)]
// ---------------------------------------------------------------------------
extern "C" void kernel_launch(void* const* d_in, const int* in_sizes, int n_in,
                              void* d_out, int out_size) {
    const float* query = (const float*)d_in[0];
    const float* values = (const float*)d_in[1];
    const float* W1 = (const float*)d_in[2];
    const float* W2 = (const float*)d_in[3];
    const float* v = (const float*)d_in[4];

    float* ctx = (float*)d_out;                 // [B, D]
    float* weights = (float*)d_out + BB * DD;   // [B, S]

    qp_kernel<<<dim3(BB, HH / 256), 256>>>(query, W2);
    scores_kernel<<<(BB * SS) / TS, 256>>>(values, W1, v, weights);
    softmax_kernel<<<BB, 256>>>(weights);
    context_kernel<<<dim3(BB, DD / 256), 256>>>(values, weights, ctx);
}

// round 7
// speedup vs baseline: 2.9023x; 2.9023x over previous
#include <cuda_runtime.h>
#include <cuda_fp16.h>
#include <math.h>
#include <stdint.h>

#define BB 32
#define SS 2048
#define DD 1024
#define HH 1024
#define BS (BB * SS)

// ---------------- device scratch ----------------
__device__ __half g_Vhi[(size_t)BB * SS * DD];   // 128 MB
__device__ __half g_Vlo[(size_t)BB * SS * DD];   // 128 MB
__device__ __half g_W1T_hi[(size_t)HH * DD];     // 2 MB  [h][d]
__device__ __half g_W1T_lo[(size_t)HH * DD];     // 2 MB
__device__ float g_qp[BB * HH];
__device__ float g_scores_part[8 * BS];          // 2 MB
__device__ float g_ctx_part[8 * BB * DD];        // 1 MB

// ---------------- PTX helpers (all baseline ISA, sm_80+) ----------------
__device__ __forceinline__ uint32_t smem_u32(const void* p) {
    uint32_t a;
    asm("{ .reg .u64 t; cvta.to.shared.u64 t, %1; cvt.u32.u64 %0, t; }" : "=r"(a) : "l"(p));
    return a;
}
#define CP_ASYNC16(dst, src) \
    asm volatile("cp.async.cg.shared.global [%0], [%1], 16;" :: "r"((uint32_t)(dst)), "l"(src) : "memory")
#define CP_COMMIT() asm volatile("cp.async.commit_group;" ::: "memory")
#define CP_WAIT1()  asm volatile("cp.async.wait_group 1;" ::: "memory")
#define CP_WAIT0()  asm volatile("cp.async.wait_group 0;" ::: "memory")

__device__ __forceinline__ void ldmx4(uint32_t* r, uint32_t addr) {
    asm volatile("ldmatrix.sync.aligned.m8n8.x4.shared.b16 {%0,%1,%2,%3}, [%4];"
                 : "=r"(r[0]), "=r"(r[1]), "=r"(r[2]), "=r"(r[3]) : "r"(addr));
}
__device__ __forceinline__ void mma16816(float* c, const uint32_t* a, const uint32_t* b) {
    asm volatile("mma.sync.aligned.m16n8k16.row.col.f32.f16.f16.f32 "
                 "{%0,%1,%2,%3}, {%4,%5,%6,%7}, {%8,%9}, {%0,%1,%2,%3};"
                 : "+f"(c[0]), "+f"(c[1]), "+f"(c[2]), "+f"(c[3])
                 : "r"(a[0]), "r"(a[1]), "r"(a[2]), "r"(a[3]), "r"(b[0]), "r"(b[1]));
}

// smem layout (bytes). Rows padded to 80 B (40 halves) -> conflict-free ldmatrix.
#define ROWB   80
#define BUF_SZ (128 * ROWB)       // 10240
#define A_HI   0
#define A_LO   (BUF_SZ)
#define B_HI   (2 * BUF_SZ)
#define B_LO   (3 * BUF_SZ)
#define STG_SZ (4 * BUF_SZ)       // 40960
#define QP_OFF (2 * STG_SZ)       // 81920
#define VV_OFF (QP_OFF + 512)
#define RED_OFF (VV_OFF + 512)
#define SMEM_TOTAL (RED_OFF + 1024)   // 83968

// ---------------------------------------------------------------------------
// Kernel 0a: split values -> fp16 hi/lo
// ---------------------------------------------------------------------------
__global__ void __launch_bounds__(256) split_values_kernel(const float* __restrict__ values) {
    size_t base = (size_t)blockIdx.x * 4096;
    #pragma unroll
    for (int i = 0; i < 4; i++) {
        size_t g = base + (size_t)(i * 256 + threadIdx.x) * 4;
        float4 x = *reinterpret_cast<const float4*>(values + g);
        __half h0 = __float2half_rn(x.x), h1 = __float2half_rn(x.y);
        __half h2 = __float2half_rn(x.z), h3 = __float2half_rn(x.w);
        __half l0 = __float2half_rn(x.x - __half2float(h0));
        __half l1 = __float2half_rn(x.y - __half2float(h1));
        __half l2 = __float2half_rn(x.z - __half2float(h2));
        __half l3 = __float2half_rn(x.w - __half2float(h3));
        *reinterpret_cast<__half2*>(g_Vhi + g)     = __half2(h0, h1);
        *reinterpret_cast<__half2*>(g_Vhi + g + 2) = __half2(h2, h3);
        *reinterpret_cast<__half2*>(g_Vlo + g)     = __half2(l0, l1);
        *reinterpret_cast<__half2*>(g_Vlo + g + 2) = __half2(l2, l3);
    }
}

// ---------------------------------------------------------------------------
// Kernel 0b: W1[d][h] -> W1T[h][d] split into fp16 hi/lo (64x64 tiles)
// ---------------------------------------------------------------------------
__global__ void __launch_bounds__(256) split_w1t_kernel(const float* __restrict__ W1) {
    __shared__ float tile[64][65];
    int d0 = blockIdx.x * 64, h0 = blockIdx.y * 64;
    int r0 = threadIdx.x >> 6;        // 0..3
    int c = threadIdx.x & 63;         // 0..63
    #pragma unroll
    for (int i = 0; i < 16; i++) {
        int row = i * 4 + r0;
        tile[row][c] = W1[(size_t)(d0 + row) * HH + h0 + c];
    }
    __syncthreads();
    #pragma unroll
    for (int i = 0; i < 16; i++) {
        int hrow = i * 4 + r0;
        float x = tile[c][hrow];      // = W1[d0+c][h0+hrow]
        __half hi = __float2half_rn(x);
        __half lo = __float2half_rn(x - __half2float(hi));
        size_t o = (size_t)(h0 + hrow) * DD + d0 + c;
        g_W1T_hi[o] = hi;
        g_W1T_lo[o] = lo;
    }
}

// ---------------------------------------------------------------------------
// Kernel 1: query_proj[b,h] = sum_d query[b,d] * W2[d,h]  (fp32, tiny)
// ---------------------------------------------------------------------------
__global__ void __launch_bounds__(256) qp_kernel(const float* __restrict__ query,
                                                 const float* __restrict__ W2) {
    int b = blockIdx.x;
    int h = blockIdx.y * 256 + threadIdx.x;
    __shared__ float qs[DD];
    for (int d = threadIdx.x; d < DD; d += 256) qs[d] = query[b * DD + d];
    __syncthreads();
    float a0 = 0.f, a1 = 0.f, a2 = 0.f, a3 = 0.f;
    #pragma unroll 4
    for (int d = 0; d < DD; d += 4) {
        a0 += qs[d + 0] * W2[(size_t)(d + 0) * HH + h];
        a1 += qs[d + 1] * W2[(size_t)(d + 1) * HH + h];
        a2 += qs[d + 2] * W2[(size_t)(d + 2) * HH + h];
        a3 += qs[d + 3] * W2[(size_t)(d + 3) * HH + h];
    }
    g_qp[b * HH + h] = (a0 + a1) + (a2 + a3);
}

// ---------------------------------------------------------------------------
// Kernel 2: scores via fp16-split HMMA GEMM + fused tanh*v epilogue.
// grid (8 h-tiles [fast], 512 m-tiles). Block 256 thr = 8 warps (4 m x 2 n),
// block tile 128x128, warp tile 32x64, K chunks of 32, cp.async dbl-buffer.
// Writes per-h-tile score partials; softmax sums them.
// ---------------------------------------------------------------------------
__device__ __forceinline__ void load_chunk(uint32_t stg,
                                           const __half* __restrict__ gAhi,
                                           const __half* __restrict__ gAlo,
                                           const __half* __restrict__ gBhi,
                                           const __half* __restrict__ gBlo,
                                           int d0, int tid) {
    int row = tid >> 1;
    int c0 = (tid & 1) * 2;                       // 16B-chunk index 0 or 2
    uint32_t so = (uint32_t)(row * ROWB + c0 * 16);
    size_t go = (size_t)row * DD + d0 + c0 * 8;
    CP_ASYNC16(stg + A_HI + so,      gAhi + go);
    CP_ASYNC16(stg + A_HI + so + 16, gAhi + go + 8);
    CP_ASYNC16(stg + A_LO + so,      gAlo + go);
    CP_ASYNC16(stg + A_LO + so + 16, gAlo + go + 8);
    CP_ASYNC16(stg + B_HI + so,      gBhi + go);
    CP_ASYNC16(stg + B_HI + so + 16, gBhi + go + 8);
    CP_ASYNC16(stg + B_LO + so,      gBlo + go);
    CP_ASYNC16(stg + B_LO + so + 16, gBlo + go + 8);
}

__global__ void __launch_bounds__(256, 1) scores_hmma_kernel(const float* __restrict__ vvec) {
    extern __shared__ __align__(16) char smem[];
    const uint32_t sb = smem_u32(smem);
    const int tid = threadIdx.x;
    const int wid = tid >> 5;
    const int lane = tid & 31;
    const int wm = wid >> 1;          // 0..3 (m dim)
    const int wn = wid & 1;           // 0..1 (n dim)
    const int m_w = wm * 32;
    const int n_w = wn * 64;

    const int h0 = blockIdx.x * 128;
    const int m0 = blockIdx.y * 128;
    const int b = m0 / SS;

    float* qp_sh = reinterpret_cast<float*>(smem + QP_OFF);
    float* v_sh  = reinterpret_cast<float*>(smem + VV_OFF);
    float* red   = reinterpret_cast<float*>(smem + RED_OFF);
    if (tid < 128) {
        qp_sh[tid] = g_qp[b * HH + h0 + tid];
        v_sh[tid]  = vvec[h0 + tid];
    }

    const __half* gAhi = g_Vhi + (size_t)m0 * DD;
    const __half* gAlo = g_Vlo + (size_t)m0 * DD;
    const __half* gBhi = g_W1T_hi + (size_t)h0 * DD;
    const __half* gBlo = g_W1T_lo + (size_t)h0 * DD;

    // ldmatrix address components (within a stage)
    const int l15 = lane & 15;
    const int lhi = lane >> 4;
    const uint32_t a_base0 = (uint32_t)((m_w + 0 * 16 + l15) * ROWB + lhi * 16);
    const uint32_t a_base1 = (uint32_t)((m_w + 1 * 16 + l15) * ROWB + lhi * 16);
    uint32_t b_base[4];
    #pragma unroll
    for (int ng = 0; ng < 4; ng++)
        b_base[ng] = (uint32_t)((n_w + ng * 16 + l15) * ROWB + lhi * 16);

    float c[2][8][4];
    #pragma unroll
    for (int mb = 0; mb < 2; mb++)
        #pragma unroll
        for (int nb = 0; nb < 8; nb++)
            #pragma unroll
            for (int r = 0; r < 4; r++) c[mb][nb][r] = 0.f;

    load_chunk(sb,          gAhi, gAlo, gBhi, gBlo, 0, tid);  CP_COMMIT();
    load_chunk(sb + STG_SZ, gAhi, gAlo, gBhi, gBlo, 32, tid); CP_COMMIT();

    for (int ch = 0; ch < 32; ch++) {
        if (ch < 30) { CP_WAIT1(); } else { CP_WAIT0(); }
        __syncthreads();
        const uint32_t stg = sb + (ch & 1) * STG_SZ;

        #pragma unroll
        for (int ks = 0; ks < 2; ks++) {
            const uint32_t ko = ks * 32;   // 16 halves = 32 bytes
            uint32_t ahi[2][4], alo[2][4];
            ldmx4(ahi[0], stg + A_HI + a_base0 + ko);
            ldmx4(ahi[1], stg + A_HI + a_base1 + ko);
            ldmx4(alo[0], stg + A_LO + a_base0 + ko);
            ldmx4(alo[1], stg + A_LO + a_base1 + ko);
            uint32_t bhi[8][2], blo[8][2];
            #pragma unroll
            for (int ng = 0; ng < 4; ng++) {
                uint32_t q[4];
                ldmx4(q, stg + B_HI + b_base[ng] + ko);
                bhi[2 * ng][0] = q[0]; bhi[2 * ng + 1][0] = q[1];
                bhi[2 * ng][1] = q[2]; bhi[2 * ng + 1][1] = q[3];
                ldmx4(q, stg + B_LO + b_base[ng] + ko);
                blo[2 * ng][0] = q[0]; blo[2 * ng + 1][0] = q[1];
                blo[2 * ng][1] = q[2]; blo[2 * ng + 1][1] = q[3];
            }
            #pragma unroll
            for (int mb = 0; mb < 2; mb++)
                #pragma unroll
                for (int nb = 0; nb < 8; nb++) {
                    mma16816(c[mb][nb], ahi[mb], bhi[nb]);
                    mma16816(c[mb][nb], ahi[mb], blo[nb]);
                    mma16816(c[mb][nb], alo[mb], bhi[nb]);
                }
        }
        __syncthreads();
        if (ch + 2 < 32) {
            load_chunk(sb + (ch & 1) * STG_SZ, gAhi, gAlo, gBhi, gBlo, (ch + 2) * 32, tid);
            CP_COMMIT();
        }
    }

    // ---- epilogue: score partial = sum_h v[h]*tanh(c + qp[h]) ----
    float racc[2][2] = {{0.f, 0.f}, {0.f, 0.f}};
    #pragma unroll
    for (int mb = 0; mb < 2; mb++)
        #pragma unroll
        for (int nb = 0; nb < 8; nb++) {
            int colb = n_w + nb * 8 + 2 * (lane & 3);
            float q0 = qp_sh[colb], q1 = qp_sh[colb + 1];
            float v0 = v_sh[colb], v1 = v_sh[colb + 1];
            racc[mb][0] += v0 * tanhf(c[mb][nb][0] + q0) + v1 * tanhf(c[mb][nb][1] + q1);
            racc[mb][1] += v0 * tanhf(c[mb][nb][2] + q0) + v1 * tanhf(c[mb][nb][3] + q1);
        }
    #pragma unroll
    for (int off = 1; off <= 2; off <<= 1) {
        #pragma unroll
        for (int mb = 0; mb < 2; mb++) {
            racc[mb][0] += __shfl_xor_sync(0xffffffffu, racc[mb][0], off);
            racc[mb][1] += __shfl_xor_sync(0xffffffffu, racc[mb][1], off);
        }
    }
    if ((lane & 3) == 0) {
        int g = lane >> 2;
        #pragma unroll
        for (int mb = 0; mb < 2; mb++) {
            red[(m_w + mb * 16 + g) * 2 + wn] = racc[mb][0];
            red[(m_w + mb * 16 + g + 8) * 2 + wn] = racc[mb][1];
        }
    }
    __syncthreads();
    if (tid < 128)
        g_scores_part[(size_t)blockIdx.x * BS + m0 + tid] = red[tid * 2] + red[tid * 2 + 1];
}

// ---------------------------------------------------------------------------
// Kernel 3: sum 8 partials + softmax over S per batch row
// ---------------------------------------------------------------------------
__global__ void __launch_bounds__(256) softmax_kernel(float* __restrict__ w) {
    int b = blockIdx.x;
    __shared__ float row[SS];
    __shared__ float sdata[256];
    int tid = threadIdx.x;

    for (int s = tid; s < SS; s += 256) {
        float acc = 0.f;
        #pragma unroll
        for (int p = 0; p < 8; p++) acc += g_scores_part[(size_t)p * BS + b * SS + s];
        row[s] = acc;
    }
    __syncthreads();

    float m = -INFINITY;
    for (int s = tid; s < SS; s += 256) m = fmaxf(m, row[s]);
    sdata[tid] = m;
    __syncthreads();
    for (int o = 128; o > 0; o >>= 1) {
        if (tid < o) sdata[tid] = fmaxf(sdata[tid], sdata[tid + o]);
        __syncthreads();
    }
    m = sdata[0];
    __syncthreads();

    float sum = 0.f;
    for (int s = tid; s < SS; s += 256) {
        float e = expf(row[s] - m);
        row[s] = e;
        sum += e;
    }
    sdata[tid] = sum;
    __syncthreads();
    for (int o = 128; o > 0; o >>= 1) {
        if (tid < o) sdata[tid] += sdata[tid + o];
        __syncthreads();
    }
    float inv = 1.f / sdata[0];
    for (int s = tid; s < SS; s += 256) w[(size_t)b * SS + s] = row[s] * inv;
}

// ---------------------------------------------------------------------------
// Kernel 4: context partials (S split 8 ways) + reduce
// ---------------------------------------------------------------------------
__global__ void __launch_bounds__(256) context_part_kernel(const float* __restrict__ values,
                                                           const float* __restrict__ w) {
    int b = blockIdx.x;
    int split = blockIdx.y;
    int s0 = split * 256;
    __shared__ float ws[256];
    ws[threadIdx.x] = w[(size_t)b * SS + s0 + threadIdx.x];
    __syncthreads();
    int d4 = threadIdx.x * 4;
    const float* vb = values + (size_t)b * SS * DD + (size_t)s0 * DD + d4;
    float4 acc = make_float4(0.f, 0.f, 0.f, 0.f);
    #pragma unroll 4
    for (int s = 0; s < 256; s++) {
        float wv = ws[s];
        float4 x = *reinterpret_cast<const float4*>(vb + (size_t)s * DD);
        acc.x += wv * x.x; acc.y += wv * x.y; acc.z += wv * x.z; acc.w += wv * x.w;
    }
    *reinterpret_cast<float4*>(g_ctx_part + ((size_t)split * BB + b) * DD + d4) = acc;
}

__global__ void __launch_bounds__(256) context_reduce_kernel(float* __restrict__ ctx) {
    int b = blockIdx.x;
    int d4 = threadIdx.x * 4;
    float4 acc = make_float4(0.f, 0.f, 0.f, 0.f);
    #pragma unroll
    for (int sp = 0; sp < 8; sp++) {
        float4 x = *reinterpret_cast<const float4*>(g_ctx_part + ((size_t)sp * BB + b) * DD + d4);
        acc.x += x.x; acc.y += x.y; acc.z += x.z; acc.w += x.w;
    }
    *reinterpret_cast<float4*>(ctx + (size_t)b * DD + d4) = acc;
}

// ---------------------------------------------------------------------------
// launch: inputs: query, values, W1, W2, v
// output: [context (B*D) | attention_weights (B*S)]
// ---------------------------------------------------------------------------
extern "C" void kernel_launch(void* const* d_in, const int* in_sizes, int n_in,
                              void* d_out, int out_size) {
    const float* query = (const float*)d_in[0];
    const float* values = (const float*)d_in[1];
    const float* W1 = (const float*)d_in[2];
    const float* W2 = (const float*)d_in[3];
    const float* v = (const float*)d_in[4];

    float* ctx = (float*)d_out;                 // [B, D]
    float* weights = (float*)d_out + BB * DD;   // [B, S]

    cudaFuncSetAttribute(scores_hmma_kernel,
                         cudaFuncAttributeMaxDynamicSharedMemorySize, SMEM_TOTAL);

    split_values_kernel<<<16384, 256>>>(values);
    split_w1t_kernel<<<dim3(DD / 64, HH / 64), 256>>>(W1);
    qp_kernel<<<dim3(BB, HH / 256), 256>>>(query, W2);
    scores_hmma_kernel<<<dim3(8, 512), 256, SMEM_TOTAL>>>(v);
    softmax_kernel<<<BB, 256>>>(weights);
    context_part_kernel<<<dim3(BB, 8), 256>>>(values, weights);
    context_reduce_kernel<<<BB, 256>>>(ctx);
}

// round 10
// speedup vs baseline: 2.9556x; 1.0184x over previous
#include <cuda_runtime.h>
#include <cuda_fp16.h>
#include <math.h>
#include <stdint.h>

#define BB 32
#define SS 2048
#define DD 1024
#define HH 1024
#define BS (BB * SS)

// ---------------- device scratch ----------------
__device__ __half g_Vhi[(size_t)BB * SS * DD];   // 128 MB
__device__ __half g_Vlo[(size_t)BB * SS * DD];   // 128 MB
__device__ __half g_W1T_hi[(size_t)HH * DD];     // 2 MB  [h][d]
__device__ __half g_W1T_lo[(size_t)HH * DD];     // 2 MB
__device__ float g_qp[BB * HH];
__device__ float g_scores_part[4 * BS];          // 1 MB
__device__ float g_ctx_part[8 * BB * DD];        // 1 MB

// ---------------- PTX helpers (baseline ISA, sm_80+) ----------------
__device__ __forceinline__ uint32_t smem_u32(const void* p) {
    uint32_t a;
    asm("{ .reg .u64 t; cvta.to.shared.u64 t, %1; cvt.u32.u64 %0, t; }" : "=r"(a) : "l"(p));
    return a;
}
#define CP_ASYNC16(dst, src) \
    asm volatile("cp.async.cg.shared.global [%0], [%1], 16;" :: "r"((uint32_t)(dst)), "l"(src) : "memory")
#define CP_COMMIT() asm volatile("cp.async.commit_group;" ::: "memory")
#define CP_WAIT2()  asm volatile("cp.async.wait_group 2;" ::: "memory")
#define CP_WAIT1()  asm volatile("cp.async.wait_group 1;" ::: "memory")
#define CP_WAIT0()  asm volatile("cp.async.wait_group 0;" ::: "memory")

__device__ __forceinline__ void ldmx4(uint32_t* r, uint32_t addr) {
    asm volatile("ldmatrix.sync.aligned.m8n8.x4.shared.b16 {%0,%1,%2,%3}, [%4];"
                 : "=r"(r[0]), "=r"(r[1]), "=r"(r[2]), "=r"(r[3]) : "r"(addr));
}
__device__ __forceinline__ void mma16816(float* c, const uint32_t* a, const uint32_t* b) {
    asm volatile("mma.sync.aligned.m16n8k16.row.col.f32.f16.f16.f32 "
                 "{%0,%1,%2,%3}, {%4,%5,%6,%7}, {%8,%9}, {%0,%1,%2,%3};"
                 : "+f"(c[0]), "+f"(c[1]), "+f"(c[2]), "+f"(c[3])
                 : "r"(a[0]), "r"(a[1]), "r"(a[2]), "r"(a[3]), "r"(b[0]), "r"(b[1]));
}

// Fast accurate tanh: 2 MUFU + few ALU, abs err ~3e-6 (scores ~O(10) -> fine)
__device__ __forceinline__ float tanh_fast(float x) {
    float xc = fminf(fmaxf(x, -20.f), 20.f);
    float t = __expf(2.f * xc);
    return 1.f - __fdividef(2.f, t + 1.f);
}

// smem layout (bytes). Rows padded to 80 B -> conflict-free ldmatrix.
#define ROWB    80
#define A_BUF   (128 * ROWB)      // 10240
#define B_BUF   (256 * ROWB)      // 20480
#define A_HI    0
#define A_LO    (A_BUF)
#define B_HI    (2 * A_BUF)
#define B_LO    (2 * A_BUF + B_BUF)
#define STG_SZ  (2 * A_BUF + 2 * B_BUF)   // 61440
#define QP_OFF  (3 * STG_SZ)              // 184320
#define VV_OFF  (QP_OFF + 1024)
#define RED_OFF (VV_OFF + 1024)
#define SMEM_TOTAL (RED_OFF + 2048)       // 188416

// ---------------------------------------------------------------------------
// Kernel 0a: split values -> fp16 hi/lo
// ---------------------------------------------------------------------------
__global__ void __launch_bounds__(256) split_values_kernel(const float* __restrict__ values) {
    size_t base = (size_t)blockIdx.x * 4096;
    #pragma unroll
    for (int i = 0; i < 4; i++) {
        size_t g = base + (size_t)(i * 256 + threadIdx.x) * 4;
        float4 x = *reinterpret_cast<const float4*>(values + g);
        __half h0 = __float2half_rn(x.x), h1 = __float2half_rn(x.y);
        __half h2 = __float2half_rn(x.z), h3 = __float2half_rn(x.w);
        __half l0 = __float2half_rn(x.x - __half2float(h0));
        __half l1 = __float2half_rn(x.y - __half2float(h1));
        __half l2 = __float2half_rn(x.z - __half2float(h2));
        __half l3 = __float2half_rn(x.w - __half2float(h3));
        *reinterpret_cast<__half2*>(g_Vhi + g)     = __half2(h0, h1);
        *reinterpret_cast<__half2*>(g_Vhi + g + 2) = __half2(h2, h3);
        *reinterpret_cast<__half2*>(g_Vlo + g)     = __half2(l0, l1);
        *reinterpret_cast<__half2*>(g_Vlo + g + 2) = __half2(l2, l3);
    }
}

// ---------------------------------------------------------------------------
// Kernel 0b: W1[d][h] -> W1T[h][d] split into fp16 hi/lo (64x64 tiles)
// ---------------------------------------------------------------------------
__global__ void __launch_bounds__(256) split_w1t_kernel(const float* __restrict__ W1) {
    __shared__ float tile[64][65];
    int d0 = blockIdx.x * 64, h0 = blockIdx.y * 64;
    int r0 = threadIdx.x >> 6;
    int c = threadIdx.x & 63;
    #pragma unroll
    for (int i = 0; i < 16; i++) {
        int row = i * 4 + r0;
        tile[row][c] = W1[(size_t)(d0 + row) * HH + h0 + c];
    }
    __syncthreads();
    #pragma unroll
    for (int i = 0; i < 16; i++) {
        int hrow = i * 4 + r0;
        float x = tile[c][hrow];
        __half hi = __float2half_rn(x);
        __half lo = __float2half_rn(x - __half2float(hi));
        size_t o = (size_t)(h0 + hrow) * DD + d0 + c;
        g_W1T_hi[o] = hi;
        g_W1T_lo[o] = lo;
    }
}

// ---------------------------------------------------------------------------
// Kernel 1: query_proj (fp32, tiny)
// ---------------------------------------------------------------------------
__global__ void __launch_bounds__(256) qp_kernel(const float* __restrict__ query,
                                                 const float* __restrict__ W2) {
    int b = blockIdx.x;
    int h = blockIdx.y * 256 + threadIdx.x;
    __shared__ float qs[DD];
    for (int d = threadIdx.x; d < DD; d += 256) qs[d] = query[b * DD + d];
    __syncthreads();
    float a0 = 0.f, a1 = 0.f, a2 = 0.f, a3 = 0.f;
    #pragma unroll 4
    for (int d = 0; d < DD; d += 4) {
        a0 += qs[d + 0] * W2[(size_t)(d + 0) * HH + h];
        a1 += qs[d + 1] * W2[(size_t)(d + 1) * HH + h];
        a2 += qs[d + 2] * W2[(size_t)(d + 2) * HH + h];
        a3 += qs[d + 3] * W2[(size_t)(d + 3) * HH + h];
    }
    g_qp[b * HH + h] = (a0 + a1) + (a2 + a3);
}

// ---------------------------------------------------------------------------
// Kernel 2: scores via fp16-split HMMA. grid(4 h-tiles, 512 m-tiles),
// 512 thr = 16 warps (4m x 4n), block tile 128x256, warp tile 32x64,
// K chunks of 32, 3-stage cp.async pipeline, ONE sync per chunk.
// ---------------------------------------------------------------------------
__device__ __forceinline__ void load_chunk(uint32_t stg,
                                           const __half* __restrict__ gAhi,
                                           const __half* __restrict__ gAlo,
                                           const __half* __restrict__ gBhi,
                                           const __half* __restrict__ gBlo,
                                           int d0, int tid) {
    // A: 128 rows x 4 segs (one (row,seg) per thread)
    {
        int row = tid >> 2, seg = tid & 3;
        uint32_t so = (uint32_t)(row * ROWB + seg * 16);
        size_t go = (size_t)row * DD + d0 + seg * 8;
        CP_ASYNC16(stg + A_HI + so, gAhi + go);
        CP_ASYNC16(stg + A_LO + so, gAlo + go);
    }
    // B: 256 rows x 4 segs (two (row,seg) per thread)
    #pragma unroll
    for (int i = 0; i < 2; i++) {
        int idx = i * 512 + tid;
        int row = idx >> 2, seg = idx & 3;
        uint32_t so = (uint32_t)(row * ROWB + seg * 16);
        size_t go = (size_t)row * DD + d0 + seg * 8;
        CP_ASYNC16(stg + B_HI + so, gBhi + go);
        CP_ASYNC16(stg + B_LO + so, gBlo + go);
    }
}

__global__ void __launch_bounds__(512, 1) scores_hmma_kernel(const float* __restrict__ vvec) {
    extern __shared__ __align__(16) char smem[];
    const uint32_t sb = smem_u32(smem);
    const int tid = threadIdx.x;
    const int wid = tid >> 5;
    const int lane = tid & 31;
    const int wm = wid >> 2;          // 0..3 (m)
    const int wn = wid & 3;           // 0..3 (n)
    const int m_w = wm * 32;
    const int n_w = wn * 64;

    const int h0 = blockIdx.x * 256;
    const int m0 = blockIdx.y * 128;
    const int b = m0 / SS;

    float* qp_sh = reinterpret_cast<float*>(smem + QP_OFF);
    float* v_sh  = reinterpret_cast<float*>(smem + VV_OFF);
    float* red   = reinterpret_cast<float*>(smem + RED_OFF);
    if (tid < 256) {
        qp_sh[tid] = g_qp[b * HH + h0 + tid];
        v_sh[tid]  = vvec[h0 + tid];
    }

    const __half* gAhi = g_Vhi + (size_t)m0 * DD;
    const __half* gAlo = g_Vlo + (size_t)m0 * DD;
    const __half* gBhi = g_W1T_hi + (size_t)h0 * DD;
    const __half* gBlo = g_W1T_lo + (size_t)h0 * DD;

    const int l15 = lane & 15;
    const int lhi = lane >> 4;
    const uint32_t a_base0 = (uint32_t)((m_w + l15) * ROWB + lhi * 16);
    const uint32_t a_base1 = (uint32_t)((m_w + 16 + l15) * ROWB + lhi * 16);
    uint32_t b_base[4];
    #pragma unroll
    for (int ng = 0; ng < 4; ng++)
        b_base[ng] = (uint32_t)((n_w + ng * 16 + l15) * ROWB + lhi * 16);

    float c[2][8][4];
    #pragma unroll
    for (int mb = 0; mb < 2; mb++)
        #pragma unroll
        for (int nb = 0; nb < 8; nb++)
            #pragma unroll
            for (int r = 0; r < 4; r++) c[mb][nb][r] = 0.f;

    // 3-stage prologue
    load_chunk(sb,              gAhi, gAlo, gBhi, gBlo, 0, tid);  CP_COMMIT();
    load_chunk(sb + STG_SZ,     gAhi, gAlo, gBhi, gBlo, 32, tid); CP_COMMIT();

    uint32_t stg_of[3] = {sb, sb + STG_SZ, sb + 2 * STG_SZ};

    for (int ch = 0; ch < 32; ch++) {
        __syncthreads();  // all warps done reading stage (ch+2)%3 (== (ch-1)%3)
        if (ch + 2 < 32) {
            load_chunk(stg_of[(ch + 2) % 3], gAhi, gAlo, gBhi, gBlo, (ch + 2) * 32, tid);
            CP_COMMIT();
            CP_WAIT2();
        } else if (ch == 30) { CP_WAIT1(); }
        else                 { CP_WAIT0(); }

        const uint32_t stg = stg_of[ch % 3];

        #pragma unroll
        for (int ks = 0; ks < 2; ks++) {
            const uint32_t ko = ks * 32;
            uint32_t ahi[2][4], alo[2][4];
            ldmx4(ahi[0], stg + A_HI + a_base0 + ko);
            ldmx4(ahi[1], stg + A_HI + a_base1 + ko);
            ldmx4(alo[0], stg + A_LO + a_base0 + ko);
            ldmx4(alo[1], stg + A_LO + a_base1 + ko);
            uint32_t bhi[8][2], blo[8][2];
            #pragma unroll
            for (int ng = 0; ng < 4; ng++) {
                uint32_t q[4];
                ldmx4(q, stg + B_HI + b_base[ng] + ko);
                bhi[2 * ng][0] = q[0]; bhi[2 * ng + 1][0] = q[1];
                bhi[2 * ng][1] = q[2]; bhi[2 * ng + 1][1] = q[3];
                ldmx4(q, stg + B_LO + b_base[ng] + ko);
                blo[2 * ng][0] = q[0]; blo[2 * ng + 1][0] = q[1];
                blo[2 * ng][1] = q[2]; blo[2 * ng + 1][1] = q[3];
            }
            // product-major: 16 independent MMAs between RAW-dependent pairs
            #pragma unroll
            for (int mb = 0; mb < 2; mb++)
                #pragma unroll
                for (int nb = 0; nb < 8; nb++) mma16816(c[mb][nb], ahi[mb], bhi[nb]);
            #pragma unroll
            for (int mb = 0; mb < 2; mb++)
                #pragma unroll
                for (int nb = 0; nb < 8; nb++) mma16816(c[mb][nb], ahi[mb], blo[nb]);
            #pragma unroll
            for (int mb = 0; mb < 2; mb++)
                #pragma unroll
                for (int nb = 0; nb < 8; nb++) mma16816(c[mb][nb], alo[mb], bhi[nb]);
        }
    }

    // ---- epilogue: score partial = sum_h v[h]*tanh(c + qp[h]) ----
    float racc[2][2] = {{0.f, 0.f}, {0.f, 0.f}};
    #pragma unroll
    for (int mb = 0; mb < 2; mb++)
        #pragma unroll
        for (int nb = 0; nb < 8; nb++) {
            int colb = n_w + nb * 8 + 2 * (lane & 3);
            float q0 = qp_sh[colb], q1 = qp_sh[colb + 1];
            float v0 = v_sh[colb], v1 = v_sh[colb + 1];
            racc[mb][0] += v0 * tanh_fast(c[mb][nb][0] + q0) + v1 * tanh_fast(c[mb][nb][1] + q1);
            racc[mb][1] += v0 * tanh_fast(c[mb][nb][2] + q0) + v1 * tanh_fast(c[mb][nb][3] + q1);
        }
    #pragma unroll
    for (int off = 1; off <= 2; off <<= 1) {
        #pragma unroll
        for (int mb = 0; mb < 2; mb++) {
            racc[mb][0] += __shfl_xor_sync(0xffffffffu, racc[mb][0], off);
            racc[mb][1] += __shfl_xor_sync(0xffffffffu, racc[mb][1], off);
        }
    }
    __syncthreads();
    if ((lane & 3) == 0) {
        int g = lane >> 2;
        #pragma unroll
        for (int mb = 0; mb < 2; mb++) {
            red[(m_w + mb * 16 + g) * 4 + wn] = racc[mb][0];
            red[(m_w + mb * 16 + g + 8) * 4 + wn] = racc[mb][1];
        }
    }
    __syncthreads();
    if (tid < 128)
        g_scores_part[(size_t)blockIdx.x * BS + m0 + tid] =
            (red[tid * 4] + red[tid * 4 + 1]) + (red[tid * 4 + 2] + red[tid * 4 + 3]);
}

// ---------------------------------------------------------------------------
// Kernel 3: sum 4 partials + softmax over S per batch row
// ---------------------------------------------------------------------------
__global__ void __launch_bounds__(256) softmax_kernel(float* __restrict__ w) {
    int b = blockIdx.x;
    __shared__ float row[SS];
    __shared__ float sdata[256];
    int tid = threadIdx.x;

    for (int s = tid; s < SS; s += 256) {
        float acc = 0.f;
        #pragma unroll
        for (int p = 0; p < 4; p++) acc += g_scores_part[(size_t)p * BS + b * SS + s];
        row[s] = acc;
    }
    __syncthreads();

    float m = -INFINITY;
    for (int s = tid; s < SS; s += 256) m = fmaxf(m, row[s]);
    sdata[tid] = m;
    __syncthreads();
    for (int o = 128; o > 0; o >>= 1) {
        if (tid < o) sdata[tid] = fmaxf(sdata[tid], sdata[tid + o]);
        __syncthreads();
    }
    m = sdata[0];
    __syncthreads();

    float sum = 0.f;
    for (int s = tid; s < SS; s += 256) {
        float e = expf(row[s] - m);
        row[s] = e;
        sum += e;
    }
    sdata[tid] = sum;
    __syncthreads();
    for (int o = 128; o > 0; o >>= 1) {
        if (tid < o) sdata[tid] += sdata[tid + o];
        __syncthreads();
    }
    float inv = 1.f / sdata[0];
    for (int s = tid; s < SS; s += 256) w[(size_t)b * SS + s] = row[s] * inv;
}

// ---------------------------------------------------------------------------
// Kernel 4: context partials (S split 8 ways) + reduce
// ---------------------------------------------------------------------------
__global__ void __launch_bounds__(256) context_part_kernel(const float* __restrict__ values,
                                                           const float* __restrict__ w) {
    int b = blockIdx.x;
    int split = blockIdx.y;
    int s0 = split * 256;
    __shared__ float ws[256];
    ws[threadIdx.x] = w[(size_t)b * SS + s0 + threadIdx.x];
    __syncthreads();
    int d4 = threadIdx.x * 4;
    const float* vb = values + (size_t)b * SS * DD + (size_t)s0 * DD + d4;
    float4 acc = make_float4(0.f, 0.f, 0.f, 0.f);
    #pragma unroll 4
    for (int s = 0; s < 256; s++) {
        float wv = ws[s];
        float4 x = *reinterpret_cast<const float4*>(vb + (size_t)s * DD);
        acc.x += wv * x.x; acc.y += wv * x.y; acc.z += wv * x.z; acc.w += wv * x.w;
    }
    *reinterpret_cast<float4*>(g_ctx_part + ((size_t)split * BB + b) * DD + d4) = acc;
}

__global__ void __launch_bounds__(256) context_reduce_kernel(float* __restrict__ ctx) {
    int b = blockIdx.x;
    int d4 = threadIdx.x * 4;
    float4 acc = make_float4(0.f, 0.f, 0.f, 0.f);
    #pragma unroll
    for (int sp = 0; sp < 8; sp++) {
        float4 x = *reinterpret_cast<const float4*>(g_ctx_part + ((size_t)sp * BB + b) * DD + d4);
        acc.x += x.x; acc.y += x.y; acc.z += x.z; acc.w += x.w;
    }
    *reinterpret_cast<float4*>(ctx + (size_t)b * DD + d4) = acc;
}

// ---------------------------------------------------------------------------
// launch: inputs: query, values, W1, W2, v
// output: [context (B*D) | attention_weights (B*S)]
// ---------------------------------------------------------------------------
extern "C" void kernel_launch(void* const* d_in, const int* in_sizes, int n_in,
                              void* d_out, int out_size) {
    const float* query = (const float*)d_in[0];
    const float* values = (const float*)d_in[1];
    const float* W1 = (const float*)d_in[2];
    const float* W2 = (const float*)d_in[3];
    const float* v = (const float*)d_in[4];

    float* ctx = (float*)d_out;                 // [B, D]
    float* weights = (float*)d_out + BB * DD;   // [B, S]

    cudaFuncSetAttribute(scores_hmma_kernel,
                         cudaFuncAttributeMaxDynamicSharedMemorySize, SMEM_TOTAL);

    split_values_kernel<<<16384, 256>>>(values);
    split_w1t_kernel<<<dim3(DD / 64, HH / 64), 256>>>(W1);
    qp_kernel<<<dim3(BB, HH / 256), 256>>>(query, W2);
    scores_hmma_kernel<<<dim3(4, 512), 512, SMEM_TOTAL>>>(v);
    softmax_kernel<<<BB, 256>>>(weights);
    context_part_kernel<<<dim3(BB, 8), 256>>>(values, weights);
    context_reduce_kernel<<<BB, 256>>>(ctx);
}

// round 12
// speedup vs baseline: 3.1688x; 1.0721x over previous
#include <cuda_runtime.h>
#include <cuda_fp16.h>
#include <math.h>
#include <stdint.h>

#define BB 32
#define SS 2048
#define DD 1024
#define HH 1024
#define BS (BB * SS)

// ---------------- device scratch ----------------
__device__ __half g_Vhi[(size_t)BB * SS * DD];   // 128 MB
__device__ __half g_Vlo[(size_t)BB * SS * DD];   // 128 MB
__device__ __half g_W1T_hi[(size_t)HH * DD];     // 2 MB  [h][d]
__device__ __half g_W1T_lo[(size_t)HH * DD];     // 2 MB
__device__ float g_qp[BB * HH];
__device__ float g_scores_part[4 * BS];          // 1 MB
__device__ float g_ctx_part[8 * BB * DD];        // 1 MB

// ---------------- PTX helpers (baseline ISA, sm_80+) ----------------
__device__ __forceinline__ uint32_t smem_u32(const void* p) {
    uint32_t a;
    asm("{ .reg .u64 t; cvta.to.shared.u64 t, %1; cvt.u32.u64 %0, t; }" : "=r"(a) : "l"(p));
    return a;
}
#define CP_ASYNC16(dst, src) \
    asm volatile("cp.async.cg.shared.global [%0], [%1], 16;" :: "r"((uint32_t)(dst)), "l"(src) : "memory")
#define CP_COMMIT() asm volatile("cp.async.commit_group;" ::: "memory")
#define CP_WAIT1()  asm volatile("cp.async.wait_group 1;" ::: "memory")
#define CP_WAIT0()  asm volatile("cp.async.wait_group 0;" ::: "memory")

__device__ __forceinline__ void ldmx4(uint32_t* r, uint32_t addr) {
    asm volatile("ldmatrix.sync.aligned.m8n8.x4.shared.b16 {%0,%1,%2,%3}, [%4];"
                 : "=r"(r[0]), "=r"(r[1]), "=r"(r[2]), "=r"(r[3]) : "r"(addr));
}
__device__ __forceinline__ void mma16816(float* c, const uint32_t* a, const uint32_t* b) {
    asm volatile("mma.sync.aligned.m16n8k16.row.col.f32.f16.f16.f32 "
                 "{%0,%1,%2,%3}, {%4,%5,%6,%7}, {%8,%9}, {%0,%1,%2,%3};"
                 : "+f"(c[0]), "+f"(c[1]), "+f"(c[2]), "+f"(c[3])
                 : "r"(a[0]), "r"(a[1]), "r"(a[2]), "r"(a[3]), "r"(b[0]), "r"(b[1]));
}

// Fast accurate tanh: 2 MUFU + few ALU, abs err ~3e-6
__device__ __forceinline__ float tanh_fast(float x) {
    float xc = fminf(fmaxf(x, -20.f), 20.f);
    float t = __expf(2.f * xc);
    return 1.f - __fdividef(2.f, t + 1.f);
}

// smem layout (bytes). Rows padded to 80 B -> conflict-free ldmatrix.
#define ROWB    80
#define A_BUF   (128 * ROWB)      // 10240
#define B_BUF   (256 * ROWB)      // 20480
#define A_HI    0
#define A_LO    (A_BUF)
#define B_HI    (2 * A_BUF)
#define B_LO    (2 * A_BUF + B_BUF)
#define STG_SZ  (2 * A_BUF + 2 * B_BUF)   // 61440
#define QP_OFF  (3 * STG_SZ)              // 184320
#define VV_OFF  (QP_OFF + 1024)
#define RED_OFF (VV_OFF + 1024)
#define SMEM_TOTAL (RED_OFF + 2048)       // 188416

// ---------------------------------------------------------------------------
// Kernel 0a: split values -> fp16 hi/lo
// ---------------------------------------------------------------------------
__global__ void __launch_bounds__(256) split_values_kernel(const float* __restrict__ values) {
    size_t base = (size_t)blockIdx.x * 4096;
    #pragma unroll
    for (int i = 0; i < 4; i++) {
        size_t g = base + (size_t)(i * 256 + threadIdx.x) * 4;
        float4 x = *reinterpret_cast<const float4*>(values + g);
        __half h0 = __float2half_rn(x.x), h1 = __float2half_rn(x.y);
        __half h2 = __float2half_rn(x.z), h3 = __float2half_rn(x.w);
        __half l0 = __float2half_rn(x.x - __half2float(h0));
        __half l1 = __float2half_rn(x.y - __half2float(h1));
        __half l2 = __float2half_rn(x.z - __half2float(h2));
        __half l3 = __float2half_rn(x.w - __half2float(h3));
        *reinterpret_cast<__half2*>(g_Vhi + g)     = __half2(h0, h1);
        *reinterpret_cast<__half2*>(g_Vhi + g + 2) = __half2(h2, h3);
        *reinterpret_cast<__half2*>(g_Vlo + g)     = __half2(l0, l1);
        *reinterpret_cast<__half2*>(g_Vlo + g + 2) = __half2(l2, l3);
    }
}

// ---------------------------------------------------------------------------
// Kernel 0b: W1[d][h] -> W1T[h][d] split into fp16 hi/lo (64x64 tiles)
// ---------------------------------------------------------------------------
__global__ void __launch_bounds__(256) split_w1t_kernel(const float* __restrict__ W1) {
    __shared__ float tile[64][65];
    int d0 = blockIdx.x * 64, h0 = blockIdx.y * 64;
    int r0 = threadIdx.x >> 6;
    int c = threadIdx.x & 63;
    #pragma unroll
    for (int i = 0; i < 16; i++) {
        int row = i * 4 + r0;
        tile[row][c] = W1[(size_t)(d0 + row) * HH + h0 + c];
    }
    __syncthreads();
    #pragma unroll
    for (int i = 0; i < 16; i++) {
        int hrow = i * 4 + r0;
        float x = tile[c][hrow];
        __half hi = __float2half_rn(x);
        __half lo = __float2half_rn(x - __half2float(hi));
        size_t o = (size_t)(h0 + hrow) * DD + d0 + c;
        g_W1T_hi[o] = hi;
        g_W1T_lo[o] = lo;
    }
}

// ---------------------------------------------------------------------------
// Kernel 1: query_proj (fp32, tiny)
// ---------------------------------------------------------------------------
__global__ void __launch_bounds__(256) qp_kernel(const float* __restrict__ query,
                                                 const float* __restrict__ W2) {
    int b = blockIdx.x;
    int h = blockIdx.y * 256 + threadIdx.x;
    __shared__ float qs[DD];
    for (int d = threadIdx.x; d < DD; d += 256) qs[d] = query[b * DD + d];
    __syncthreads();
    float a0 = 0.f, a1 = 0.f, a2 = 0.f, a3 = 0.f;
    #pragma unroll 4
    for (int d = 0; d < DD; d += 4) {
        a0 += qs[d + 0] * W2[(size_t)(d + 0) * HH + h];
        a1 += qs[d + 1] * W2[(size_t)(d + 1) * HH + h];
        a2 += qs[d + 2] * W2[(size_t)(d + 2) * HH + h];
        a3 += qs[d + 3] * W2[(size_t)(d + 3) * HH + h];
    }
    g_qp[b * HH + h] = (a0 + a1) + (a2 + a3);
}

// ---------------------------------------------------------------------------
// Kernel 2: scores via fp16-split HMMA. grid(4 h-tiles, 512 m-tiles),
// 512 thr = 16 warps (4m x 4n), block tile 128x256, warp tile 32x64.
// 3-stage pipeline with CORRECT ordering: wait_group -> __syncthreads ->
// compute -> issue next loads. Pointer-incremented cp.async addressing.
// ---------------------------------------------------------------------------
__global__ void __launch_bounds__(512, 1) scores_hmma_kernel(const float* __restrict__ vvec) {
    extern __shared__ __align__(16) char smem[];
    const uint32_t sb = smem_u32(smem);
    const int tid = threadIdx.x;
    const int wid = tid >> 5;
    const int lane = tid & 31;
    const int wm = wid >> 2;          // 0..3 (m)
    const int wn = wid & 3;           // 0..3 (n)
    const int m_w = wm * 32;
    const int n_w = wn * 64;

    const int h0 = blockIdx.x * 256;
    const int m0 = blockIdx.y * 128;
    const int b = m0 / SS;

    float* qp_sh = reinterpret_cast<float*>(smem + QP_OFF);
    float* v_sh  = reinterpret_cast<float*>(smem + VV_OFF);
    float* red   = reinterpret_cast<float*>(smem + RED_OFF);
    if (tid < 256) {
        qp_sh[tid] = g_qp[b * HH + h0 + tid];
        v_sh[tid]  = vvec[h0 + tid];
    }

    // ---- per-thread load pointers (advance +32 halves per chunk) ----
    const int lrow = tid >> 2;        // 0..127
    const int lseg = tid & 3;         // 0..3
    const uint32_t a_off  = (uint32_t)(lrow * ROWB + lseg * 16);
    const uint32_t b_off0 = a_off;                                  // B row lrow
    const uint32_t b_off1 = (uint32_t)((128 + lrow) * ROWB + lseg * 16);
    const __half* pAhi  = g_Vhi    + (size_t)(m0 + lrow) * DD + lseg * 8;
    const __half* pAlo  = g_Vlo    + (size_t)(m0 + lrow) * DD + lseg * 8;
    const __half* pBhi0 = g_W1T_hi + (size_t)(h0 + lrow) * DD + lseg * 8;
    const __half* pBlo0 = g_W1T_lo + (size_t)(h0 + lrow) * DD + lseg * 8;
    const __half* pBhi1 = pBhi0 + (size_t)128 * DD;
    const __half* pBlo1 = pBlo0 + (size_t)128 * DD;

    // ---- ldmatrix base offsets (stage-relative) ----
    const int l15 = lane & 15;
    const int lhi = lane >> 4;
    const uint32_t a_base0 = (uint32_t)((m_w + l15) * ROWB + lhi * 16);
    const uint32_t a_base1 = (uint32_t)((m_w + 16 + l15) * ROWB + lhi * 16);
    uint32_t b_base[4];
    #pragma unroll
    for (int ng = 0; ng < 4; ng++)
        b_base[ng] = (uint32_t)((n_w + ng * 16 + l15) * ROWB + lhi * 16);

    float c[2][8][4];
    #pragma unroll
    for (int mb = 0; mb < 2; mb++)
        #pragma unroll
        for (int nb = 0; nb < 8; nb++)
            #pragma unroll
            for (int r = 0; r < 4; r++) c[mb][nb][r] = 0.f;

    // ---- prologue: fill stages 0 and 1 ----
    #pragma unroll
    for (int p = 0; p < 2; p++) {
        uint32_t stg = sb + p * STG_SZ;
        int adv = p * 32;
        CP_ASYNC16(stg + A_HI + a_off,  pAhi  + adv);
        CP_ASYNC16(stg + A_LO + a_off,  pAlo  + adv);
        CP_ASYNC16(stg + B_HI + b_off0, pBhi0 + adv);
        CP_ASYNC16(stg + B_LO + b_off0, pBlo0 + adv);
        CP_ASYNC16(stg + B_HI + b_off1, pBhi1 + adv);
        CP_ASYNC16(stg + B_LO + b_off1, pBlo1 + adv);
        CP_COMMIT();
    }
    pAhi += 64; pAlo += 64; pBhi0 += 64; pBlo0 += 64; pBhi1 += 64; pBlo1 += 64;

    uint32_t stg_cur = sb;                     // stage ch%3
    uint32_t stg_nxt = sb + 2 * STG_SZ;        // stage (ch+2)%3
    const uint32_t stg_hi = sb + 2 * STG_SZ;

    for (int ch = 0; ch < 32; ch++) {
        // CORRECT ordering: own-group wait, THEN barrier -> all warps' data for
        // chunk ch is complete and visible before any thread reads it. The
        // barrier also guarantees stage stg_nxt (read by all at ch-1) is free.
        if (ch == 31) { CP_WAIT0(); } else { CP_WAIT1(); }
        __syncthreads();

        // ---- compute on stg_cur ----
        #pragma unroll
        for (int ks = 0; ks < 2; ks++) {
            const uint32_t ko = ks * 32;
            uint32_t ahi[2][4], alo[2][4];
            ldmx4(ahi[0], stg_cur + A_HI + a_base0 + ko);
            ldmx4(ahi[1], stg_cur + A_HI + a_base1 + ko);
            ldmx4(alo[0], stg_cur + A_LO + a_base0 + ko);
            ldmx4(alo[1], stg_cur + A_LO + a_base1 + ko);
            uint32_t bhi[8][2];
            #pragma unroll
            for (int ng = 0; ng < 4; ng++) {
                uint32_t q[4];
                ldmx4(q, stg_cur + B_HI + b_base[ng] + ko);
                bhi[2 * ng][0] = q[0]; bhi[2 * ng + 1][0] = q[1];
                bhi[2 * ng][1] = q[2]; bhi[2 * ng + 1][1] = q[3];
            }
            // hi*hi then lo*hi (alo+bhi die after this)
            #pragma unroll
            for (int mb = 0; mb < 2; mb++)
                #pragma unroll
                for (int nb = 0; nb < 8; nb++) mma16816(c[mb][nb], ahi[mb], bhi[nb]);
            #pragma unroll
            for (int mb = 0; mb < 2; mb++)
                #pragma unroll
                for (int nb = 0; nb < 8; nb++) mma16816(c[mb][nb], alo[mb], bhi[nb]);
            // load blo fresh, then hi*lo
            uint32_t blo[8][2];
            #pragma unroll
            for (int ng = 0; ng < 4; ng++) {
                uint32_t q[4];
                ldmx4(q, stg_cur + B_LO + b_base[ng] + ko);
                blo[2 * ng][0] = q[0]; blo[2 * ng + 1][0] = q[1];
                blo[2 * ng][1] = q[2]; blo[2 * ng + 1][1] = q[3];
            }
            #pragma unroll
            for (int mb = 0; mb < 2; mb++)
                #pragma unroll
                for (int nb = 0; nb < 8; nb++) mma16816(c[mb][nb], ahi[mb], blo[nb]);
        }

        // ---- issue loads for chunk ch+2 into stg_nxt (freed by the barrier) ----
        if (ch + 2 < 32) {
            CP_ASYNC16(stg_nxt + A_HI + a_off,  pAhi);
            CP_ASYNC16(stg_nxt + A_LO + a_off,  pAlo);
            CP_ASYNC16(stg_nxt + B_HI + b_off0, pBhi0);
            CP_ASYNC16(stg_nxt + B_LO + b_off0, pBlo0);
            CP_ASYNC16(stg_nxt + B_HI + b_off1, pBhi1);
            CP_ASYNC16(stg_nxt + B_LO + b_off1, pBlo1);
            CP_COMMIT();
            pAhi += 32; pAlo += 32; pBhi0 += 32; pBlo0 += 32; pBhi1 += 32; pBlo1 += 32;
        }
        stg_cur = (stg_cur == stg_hi) ? sb : (stg_cur + STG_SZ);
        stg_nxt = (stg_nxt == stg_hi) ? sb : (stg_nxt + STG_SZ);
    }

    // ---- epilogue: score partial = sum_h v[h]*tanh(c + qp[h]) ----
    float racc[2][2] = {{0.f, 0.f}, {0.f, 0.f}};
    #pragma unroll
    for (int mb = 0; mb < 2; mb++)
        #pragma unroll
        for (int nb = 0; nb < 8; nb++) {
            int colb = n_w + nb * 8 + 2 * (lane & 3);
            float q0 = qp_sh[colb], q1 = qp_sh[colb + 1];
            float v0 = v_sh[colb], v1 = v_sh[colb + 1];
            racc[mb][0] += v0 * tanh_fast(c[mb][nb][0] + q0) + v1 * tanh_fast(c[mb][nb][1] + q1);
            racc[mb][1] += v0 * tanh_fast(c[mb][nb][2] + q0) + v1 * tanh_fast(c[mb][nb][3] + q1);
        }
    #pragma unroll
    for (int off = 1; off <= 2; off <<= 1) {
        #pragma unroll
        for (int mb = 0; mb < 2; mb++) {
            racc[mb][0] += __shfl_xor_sync(0xffffffffu, racc[mb][0], off);
            racc[mb][1] += __shfl_xor_sync(0xffffffffu, racc[mb][1], off);
        }
    }
    __syncthreads();
    if ((lane & 3) == 0) {
        int g = lane >> 2;
        #pragma unroll
        for (int mb = 0; mb < 2; mb++) {
            red[(m_w + mb * 16 + g) * 4 + wn] = racc[mb][0];
            red[(m_w + mb * 16 + g + 8) * 4 + wn] = racc[mb][1];
        }
    }
    __syncthreads();
    if (tid < 128)
        g_scores_part[(size_t)blockIdx.x * BS + m0 + tid] =
            (red[tid * 4] + red[tid * 4 + 1]) + (red[tid * 4 + 2] + red[tid * 4 + 3]);
}

// ---------------------------------------------------------------------------
// Kernel 3: sum 4 partials + softmax over S per batch row
// ---------------------------------------------------------------------------
__global__ void __launch_bounds__(256) softmax_kernel(float* __restrict__ w) {
    int b = blockIdx.x;
    __shared__ float row[SS];
    __shared__ float sdata[256];
    int tid = threadIdx.x;

    for (int s = tid; s < SS; s += 256) {
        float acc = 0.f;
        #pragma unroll
        for (int p = 0; p < 4; p++) acc += g_scores_part[(size_t)p * BS + b * SS + s];
        row[s] = acc;
    }
    __syncthreads();

    float m = -INFINITY;
    for (int s = tid; s < SS; s += 256) m = fmaxf(m, row[s]);
    sdata[tid] = m;
    __syncthreads();
    for (int o = 128; o > 0; o >>= 1) {
        if (tid < o) sdata[tid] = fmaxf(sdata[tid], sdata[tid + o]);
        __syncthreads();
    }
    m = sdata[0];
    __syncthreads();

    float sum = 0.f;
    for (int s = tid; s < SS; s += 256) {
        float e = expf(row[s] - m);
        row[s] = e;
        sum += e;
    }
    sdata[tid] = sum;
    __syncthreads();
    for (int o = 128; o > 0; o >>= 1) {
        if (tid < o) sdata[tid] += sdata[tid + o];
        __syncthreads();
    }
    float inv = 1.f / sdata[0];
    for (int s = tid; s < SS; s += 256) w[(size_t)b * SS + s] = row[s] * inv;
}

// ---------------------------------------------------------------------------
// Kernel 4: context partials (S split 8 ways) + reduce
// ---------------------------------------------------------------------------
__global__ void __launch_bounds__(256) context_part_kernel(const float* __restrict__ values,
                                                           const float* __restrict__ w) {
    int b = blockIdx.x;
    int split = blockIdx.y;
    int s0 = split * 256;
    __shared__ float ws[256];
    ws[threadIdx.x] = w[(size_t)b * SS + s0 + threadIdx.x];
    __syncthreads();
    int d4 = threadIdx.x * 4;
    const float* vb = values + (size_t)b * SS * DD + (size_t)s0 * DD + d4;
    float4 acc = make_float4(0.f, 0.f, 0.f, 0.f);
    #pragma unroll 4
    for (int s = 0; s < 256; s++) {
        float wv = ws[s];
        float4 x = *reinterpret_cast<const float4*>(vb + (size_t)s * DD);
        acc.x += wv * x.x; acc.y += wv * x.y; acc.z += wv * x.z; acc.w += wv * x.w;
    }
    *reinterpret_cast<float4*>(g_ctx_part + ((size_t)split * BB + b) * DD + d4) = acc;
}

__global__ void __launch_bounds__(256) context_reduce_kernel(float* __restrict__ ctx) {
    int b = blockIdx.x;
    int d4 = threadIdx.x * 4;
    float4 acc = make_float4(0.f, 0.f, 0.f, 0.f);
    #pragma unroll
    for (int sp = 0; sp < 8; sp++) {
        float4 x = *reinterpret_cast<const float4*>(g_ctx_part + ((size_t)sp * BB + b) * DD + d4);
        acc.x += x.x; acc.y += x.y; acc.z += x.z; acc.w += x.w;
    }
    *reinterpret_cast<float4*>(ctx + (size_t)b * DD + d4) = acc;
}

// ---------------------------------------------------------------------------
// launch: inputs: query, values, W1, W2, v
// output: [context (B*D) | attention_weights (B*S)]
// ---------------------------------------------------------------------------
extern "C" void kernel_launch(void* const* d_in, const int* in_sizes, int n_in,
                              void* d_out, int out_size) {
    const float* query = (const float*)d_in[0];
    const float* values = (const float*)d_in[1];
    const float* W1 = (const float*)d_in[2];
    const float* W2 = (const float*)d_in[3];
    const float* v = (const float*)d_in[4];

    float* ctx = (float*)d_out;                 // [B, D]
    float* weights = (float*)d_out + BB * DD;   // [B, S]

    cudaFuncSetAttribute(scores_hmma_kernel,
                         cudaFuncAttributeMaxDynamicSharedMemorySize, SMEM_TOTAL);

    split_values_kernel<<<16384, 256>>>(values);
    split_w1t_kernel<<<dim3(DD / 64, HH / 64), 256>>>(W1);
    qp_kernel<<<dim3(BB, HH / 256), 256>>>(query, W2);
    scores_hmma_kernel<<<dim3(4, 512), 512, SMEM_TOTAL>>>(v);
    softmax_kernel<<<BB, 256>>>(weights);
    context_part_kernel<<<dim3(BB, 8), 256>>>(values, weights);
    context_reduce_kernel<<<BB, 256>>>(ctx);
}

// round 14
// speedup vs baseline: 3.1736x; 1.0015x over previous
#include <cuda_runtime.h>
#include <cuda_fp16.h>
#include <math.h>
#include <stdint.h>

#define BB 32
#define SS 2048
#define DD 1024
#define HH 1024
#define BS (BB * SS)
#define HD (HH * DD)

// ---------------- device scratch ----------------
__device__ __half g_Vhi[(size_t)BB * SS * DD];   // 128 MB
__device__ __half g_Vlo[(size_t)BB * SS * DD];   // 128 MB
__device__ __half g_W[2 * (size_t)HD];           // 4 MB: [0,HD) = W1T hi, [HD,2HD) = W1T lo
__device__ float g_qp[BB * HH];
__device__ float g_scores_part[4 * BS];          // 1 MB
__device__ float g_ctx_part[8 * BB * DD];        // 1 MB

// ---------------- PTX helpers (baseline ISA, sm_80+) ----------------
__device__ __forceinline__ uint32_t smem_u32(const void* p) {
    uint32_t a;
    asm("{ .reg .u64 t; cvta.to.shared.u64 t, %1; cvt.u32.u64 %0, t; }" : "=r"(a) : "l"(p));
    return a;
}
#define CP_ASYNC16(dst, src) \
    asm volatile("cp.async.cg.shared.global [%0], [%1], 16;" :: "r"((uint32_t)(dst)), "l"(src) : "memory")
// immediate-offset variant: dst = reg+imm (bytes), src = ptr+imm (bytes)
#define CP_A16I(dst, DIMM, src, SIMM) \
    asm volatile("cp.async.cg.shared.global [%0+%1], [%2+%3], 16;" \
                 :: "r"((uint32_t)(dst)), "n"(DIMM), "l"(src), "n"(SIMM) : "memory")
#define CP_COMMIT() asm volatile("cp.async.commit_group;" ::: "memory")
#define CP_WAIT1()  asm volatile("cp.async.wait_group 1;" ::: "memory")
#define CP_WAIT0()  asm volatile("cp.async.wait_group 0;" ::: "memory")

#define LDMX4I(r, base, IMM) \
    asm volatile("ldmatrix.sync.aligned.m8n8.x4.shared.b16 {%0,%1,%2,%3}, [%4+%5];" \
                 : "=r"((r)[0]), "=r"((r)[1]), "=r"((r)[2]), "=r"((r)[3]) \
                 : "r"(base), "n"(IMM))

__device__ __forceinline__ void mma16816(float* c, const uint32_t* a, const uint32_t* b) {
    asm volatile("mma.sync.aligned.m16n8k16.row.col.f32.f16.f16.f32 "
                 "{%0,%1,%2,%3}, {%4,%5,%6,%7}, {%8,%9}, {%0,%1,%2,%3};"
                 : "+f"(c[0]), "+f"(c[1]), "+f"(c[2]), "+f"(c[3])
                 : "r"(a[0]), "r"(a[1]), "r"(a[2]), "r"(a[3]), "r"(b[0]), "r"(b[1]));
}

// Fast accurate tanh: 2 MUFU + few ALU, abs err ~3e-6
__device__ __forceinline__ float tanh_fast(float x) {
    float xc = fminf(fmaxf(x, -20.f), 20.f);
    float t = __expf(2.f * xc);
    return 1.f - __fdividef(2.f, t + 1.f);
}

// smem layout (bytes). Rows padded to 80 B -> conflict-free ldmatrix.
#define ROWB    80
#define A_BUF   (128 * ROWB)      // 10240
#define B_BUF   (256 * ROWB)      // 20480
#define A_HI    0
#define A_LO    (A_BUF)           // 10240
#define B_HI    (2 * A_BUF)       // 20480
#define B_LO    (2 * A_BUF + B_BUF)  // 40960
#define STG_SZ  (2 * A_BUF + 2 * B_BUF)   // 61440
#define QP_OFF  (3 * STG_SZ)              // 184320
#define VV_OFF  (QP_OFF + 1024)
#define RED_OFF (VV_OFF + 1024)
#define SMEM_TOTAL (RED_OFF + 2048)       // 188416

// ---------------------------------------------------------------------------
// Kernel 0a: split values -> fp16 hi/lo
// ---------------------------------------------------------------------------
__global__ void __launch_bounds__(256) split_values_kernel(const float* __restrict__ values) {
    size_t base = (size_t)blockIdx.x * 4096;
    #pragma unroll
    for (int i = 0; i < 4; i++) {
        size_t g = base + (size_t)(i * 256 + threadIdx.x) * 4;
        float4 x = *reinterpret_cast<const float4*>(values + g);
        __half h0 = __float2half_rn(x.x), h1 = __float2half_rn(x.y);
        __half h2 = __float2half_rn(x.z), h3 = __float2half_rn(x.w);
        __half l0 = __float2half_rn(x.x - __half2float(h0));
        __half l1 = __float2half_rn(x.y - __half2float(h1));
        __half l2 = __float2half_rn(x.z - __half2float(h2));
        __half l3 = __float2half_rn(x.w - __half2float(h3));
        *reinterpret_cast<__half2*>(g_Vhi + g)     = __half2(h0, h1);
        *reinterpret_cast<__half2*>(g_Vhi + g + 2) = __half2(h2, h3);
        *reinterpret_cast<__half2*>(g_Vlo + g)     = __half2(l0, l1);
        *reinterpret_cast<__half2*>(g_Vlo + g + 2) = __half2(l2, l3);
    }
}

// ---------------------------------------------------------------------------
// Kernel 0b: W1[d][h] -> W1T[h][d] split into fp16 hi/lo (64x64 tiles)
// ---------------------------------------------------------------------------
__global__ void __launch_bounds__(256) split_w1t_kernel(const float* __restrict__ W1) {
    __shared__ float tile[64][65];
    int d0 = blockIdx.x * 64, h0 = blockIdx.y * 64;
    int r0 = threadIdx.x >> 6;
    int c = threadIdx.x & 63;
    #pragma unroll
    for (int i = 0; i < 16; i++) {
        int row = i * 4 + r0;
        tile[row][c] = W1[(size_t)(d0 + row) * HH + h0 + c];
    }
    __syncthreads();
    #pragma unroll
    for (int i = 0; i < 16; i++) {
        int hrow = i * 4 + r0;
        float x = tile[c][hrow];
        __half hi = __float2half_rn(x);
        __half lo = __float2half_rn(x - __half2float(hi));
        size_t o = (size_t)(h0 + hrow) * DD + d0 + c;
        g_W[o] = hi;
        g_W[HD + o] = lo;
    }
}

// ---------------------------------------------------------------------------
// Kernel 1: query_proj (fp32, tiny)
// ---------------------------------------------------------------------------
__global__ void __launch_bounds__(256) qp_kernel(const float* __restrict__ query,
                                                 const float* __restrict__ W2) {
    int b = blockIdx.x;
    int h = blockIdx.y * 256 + threadIdx.x;
    __shared__ float qs[DD];
    for (int d = threadIdx.x; d < DD; d += 256) qs[d] = query[b * DD + d];
    __syncthreads();
    float a0 = 0.f, a1 = 0.f, a2 = 0.f, a3 = 0.f;
    #pragma unroll 4
    for (int d = 0; d < DD; d += 4) {
        a0 += qs[d + 0] * W2[(size_t)(d + 0) * HH + h];
        a1 += qs[d + 1] * W2[(size_t)(d + 1) * HH + h];
        a2 += qs[d + 2] * W2[(size_t)(d + 2) * HH + h];
        a3 += qs[d + 3] * W2[(size_t)(d + 3) * HH + h];
    }
    g_qp[b * HH + h] = (a0 + a1) + (a2 + a3);
}

// ---------------------------------------------------------------------------
// Kernel 2: scores via fp16-split HMMA. grid(4 h-tiles, 512 m-tiles),
// 512 thr = 16 warps (4m x 4n), block tile 128x256, warp tile 32x64.
// Immediate-offset LDSM/cp.async addressing; LDSM/MMA interleave; warp-
// parity ks staggering; 3-stage pipeline (wait -> barrier -> compute -> load).
// ---------------------------------------------------------------------------

// one K=16 slice: KO = 0 or 32 bytes
template<int KO>
__device__ __forceinline__ void compute_ks(uint32_t aaddr, uint32_t baddr,
                                           float c[2][8][4]) {
    uint32_t ahi[2][4], alo[2][4], q[4];
    uint32_t bhi[8][2], blo[8][2];

    // group 1: A hi + first half of B hi
    LDMX4I(ahi[0], aaddr, KO);
    LDMX4I(ahi[1], aaddr, 1280 + KO);
    LDMX4I(q, baddr, KO);
    bhi[0][0] = q[0]; bhi[1][0] = q[1]; bhi[0][1] = q[2]; bhi[1][1] = q[3];
    LDMX4I(q, baddr, 1280 + KO);
    bhi[2][0] = q[0]; bhi[3][0] = q[1]; bhi[2][1] = q[2]; bhi[3][1] = q[3];

    // 8 hi*hi MMAs on nb 0..3 (LDSM latency for group 2 hides under these)
    #pragma unroll
    for (int mb = 0; mb < 2; mb++)
        #pragma unroll
        for (int nb = 0; nb < 4; nb++) mma16816(c[mb][nb], ahi[mb], bhi[nb]);

    // group 2: rest of B hi + A lo
    LDMX4I(q, baddr, 2560 + KO);
    bhi[4][0] = q[0]; bhi[5][0] = q[1]; bhi[4][1] = q[2]; bhi[5][1] = q[3];
    LDMX4I(q, baddr, 3840 + KO);
    bhi[6][0] = q[0]; bhi[7][0] = q[1]; bhi[6][1] = q[2]; bhi[7][1] = q[3];
    LDMX4I(alo[0], aaddr, 10240 + KO);
    LDMX4I(alo[1], aaddr, 10240 + 1280 + KO);

    // 8 hi*hi MMAs on nb 4..7
    #pragma unroll
    for (int mb = 0; mb < 2; mb++)
        #pragma unroll
        for (int nb = 4; nb < 8; nb++) mma16816(c[mb][nb], ahi[mb], bhi[nb]);

    // group 3: B lo
    LDMX4I(q, baddr, 20480 + KO);
    blo[0][0] = q[0]; blo[1][0] = q[1]; blo[0][1] = q[2]; blo[1][1] = q[3];
    LDMX4I(q, baddr, 20480 + 1280 + KO);
    blo[2][0] = q[0]; blo[3][0] = q[1]; blo[2][1] = q[2]; blo[3][1] = q[3];
    LDMX4I(q, baddr, 20480 + 2560 + KO);
    blo[4][0] = q[0]; blo[5][0] = q[1]; blo[4][1] = q[2]; blo[5][1] = q[3];
    LDMX4I(q, baddr, 20480 + 3840 + KO);
    blo[6][0] = q[0]; blo[7][0] = q[1]; blo[6][1] = q[2]; blo[7][1] = q[3];

    // 16 lo*hi
    #pragma unroll
    for (int mb = 0; mb < 2; mb++)
        #pragma unroll
        for (int nb = 0; nb < 8; nb++) mma16816(c[mb][nb], alo[mb], bhi[nb]);
    // 16 hi*lo
    #pragma unroll
    for (int mb = 0; mb < 2; mb++)
        #pragma unroll
        for (int nb = 0; nb < 8; nb++) mma16816(c[mb][nb], ahi[mb], blo[nb]);
}

__global__ void __launch_bounds__(512, 1) scores_hmma_kernel(const float* __restrict__ vvec) {
    extern __shared__ __align__(16) char smem[];
    const uint32_t sb = smem_u32(smem);
    const int tid = threadIdx.x;
    const int wid = tid >> 5;
    const int lane = tid & 31;
    const int wm = wid >> 2;          // 0..3 (m)
    const int wn = wid & 3;           // 0..3 (n)
    const int m_w = wm * 32;
    const int n_w = wn * 64;

    const int h0 = blockIdx.x * 256;
    const int m0 = blockIdx.y * 128;
    const int b = m0 / SS;

    float* qp_sh = reinterpret_cast<float*>(smem + QP_OFF);
    float* v_sh  = reinterpret_cast<float*>(smem + VV_OFF);
    float* red   = reinterpret_cast<float*>(smem + RED_OFF);
    if (tid < 256) {
        qp_sh[tid] = g_qp[b * HH + h0 + tid];
        v_sh[tid]  = vvec[h0 + tid];
    }

    // ---- per-thread load pointers ----
    const int lrow = tid >> 2;        // 0..127
    const int lseg = tid & 3;         // 0..3
    const uint32_t a_off = (uint32_t)(lrow * ROWB + lseg * 16);
    const __half* pAhi = g_Vhi + (size_t)(m0 + lrow) * DD + lseg * 8;
    const __half* pAlo = g_Vlo + (size_t)(m0 + lrow) * DD + lseg * 8;
    const __half* pW   = g_W   + (size_t)(h0 + lrow) * DD + lseg * 8;

    // ---- ldmatrix stage-relative base offsets ----
    const int l15 = lane & 15;
    const int lhi = lane >> 4;
    const uint32_t a_base0 = (uint32_t)(A_HI + (m_w + l15) * ROWB + lhi * 16);
    const uint32_t b_base0 = (uint32_t)(B_HI + (n_w + l15) * ROWB + lhi * 16);

    float c[2][8][4];
    #pragma unroll
    for (int mb = 0; mb < 2; mb++)
        #pragma unroll
        for (int nb = 0; nb < 8; nb++)
            #pragma unroll
            for (int r = 0; r < 4; r++) c[mb][nb][r] = 0.f;

    // ---- prologue: fill stages 0 and 1 (plain addressing; cold path) ----
    #pragma unroll
    for (int p = 0; p < 2; p++) {
        uint32_t dst = sb + p * STG_SZ + a_off;
        int adv = p * 32;
        CP_ASYNC16(dst + 0,     pAhi + adv);
        CP_ASYNC16(dst + 10240, pAlo + adv);
        CP_ASYNC16(dst + 20480, pW + adv);                 // B hi row lrow
        CP_ASYNC16(dst + 30720, pW + adv + 128 * DD);      // B hi row lrow+128
        CP_ASYNC16(dst + 40960, pW + adv + HD);            // B lo row lrow
        CP_ASYNC16(dst + 51200, pW + adv + HD + 128 * DD); // B lo row lrow+128
        CP_COMMIT();
    }
    pAhi += 64; pAlo += 64; pW += 64;

    uint32_t stg_cur = sb;                     // stage ch%3
    uint32_t stg_nxt = sb + 2 * STG_SZ;        // stage (ch+2)%3
    const uint32_t stg_hi = sb + 2 * STG_SZ;
    const int kfirst = (wid & 1);              // warp-parity ks stagger

    for (int ch = 0; ch < 32; ch++) {
        // own-group wait THEN barrier: all warps' chunk-ch data visible; and
        // stage stg_nxt (last read by all at ch-1) is free for refill.
        if (ch == 31) { CP_WAIT0(); } else { CP_WAIT1(); }
        __syncthreads();

        const uint32_t aaddr = stg_cur + a_base0;
        const uint32_t baddr = stg_cur + b_base0;
        if (kfirst) { compute_ks<32>(aaddr, baddr, c); compute_ks<0>(aaddr, baddr, c); }
        else        { compute_ks<0>(aaddr, baddr, c);  compute_ks<32>(aaddr, baddr, c); }

        // ---- issue loads for chunk ch+2 into stg_nxt ----
        if (ch + 2 < 32) {
            uint32_t dst = stg_nxt + a_off;
            CP_A16I(dst, 0,     pAhi, 0);
            CP_A16I(dst, 10240, pAlo, 0);
            CP_A16I(dst, 20480, pW, 0);
            CP_A16I(dst, 30720, pW, 128 * DD * 2);            // +262144 B
            CP_A16I(dst, 40960, pW, HD * 2);                  // +2097152 B
            CP_A16I(dst, 51200, pW, HD * 2 + 128 * DD * 2);   // +2359296 B
            CP_COMMIT();
            pAhi += 32; pAlo += 32; pW += 32;
        }
        stg_cur = (stg_cur == stg_hi) ? sb : (stg_cur + STG_SZ);
        stg_nxt = (stg_nxt == stg_hi) ? sb : (stg_nxt + STG_SZ);
    }

    // ---- epilogue: score partial = sum_h v[h]*tanh(c + qp[h]) ----
    float racc[2][2] = {{0.f, 0.f}, {0.f, 0.f}};
    #pragma unroll
    for (int mb = 0; mb < 2; mb++)
        #pragma unroll
        for (int nb = 0; nb < 8; nb++) {
            int colb = n_w + nb * 8 + 2 * (lane & 3);
            float q0 = qp_sh[colb], q1 = qp_sh[colb + 1];
            float v0 = v_sh[colb], v1 = v_sh[colb + 1];
            racc[mb][0] += v0 * tanh_fast(c[mb][nb][0] + q0) + v1 * tanh_fast(c[mb][nb][1] + q1);
            racc[mb][1] += v0 * tanh_fast(c[mb][nb][2] + q0) + v1 * tanh_fast(c[mb][nb][3] + q1);
        }
    #pragma unroll
    for (int off = 1; off <= 2; off <<= 1) {
        #pragma unroll
        for (int mb = 0; mb < 2; mb++) {
            racc[mb][0] += __shfl_xor_sync(0xffffffffu, racc[mb][0], off);
            racc[mb][1] += __shfl_xor_sync(0xffffffffu, racc[mb][1], off);
        }
    }
    __syncthreads();
    if ((lane & 3) == 0) {
        int g = lane >> 2;
        #pragma unroll
        for (int mb = 0; mb < 2; mb++) {
            red[(m_w + mb * 16 + g) * 4 + wn] = racc[mb][0];
            red[(m_w + mb * 16 + g + 8) * 4 + wn] = racc[mb][1];
        }
    }
    __syncthreads();
    if (tid < 128)
        g_scores_part[(size_t)blockIdx.x * BS + m0 + tid] =
            (red[tid * 4] + red[tid * 4 + 1]) + (red[tid * 4 + 2] + red[tid * 4 + 3]);
}

// ---------------------------------------------------------------------------
// Kernel 3: sum 4 partials + softmax over S per batch row
// ---------------------------------------------------------------------------
__global__ void __launch_bounds__(256) softmax_kernel(float* __restrict__ w) {
    int b = blockIdx.x;
    __shared__ float row[SS];
    __shared__ float sdata[256];
    int tid = threadIdx.x;

    for (int s = tid; s < SS; s += 256) {
        float acc = 0.f;
        #pragma unroll
        for (int p = 0; p < 4; p++) acc += g_scores_part[(size_t)p * BS + b * SS + s];
        row[s] = acc;
    }
    __syncthreads();

    float m = -INFINITY;
    for (int s = tid; s < SS; s += 256) m = fmaxf(m, row[s]);
    sdata[tid] = m;
    __syncthreads();
    for (int o = 128; o > 0; o >>= 1) {
        if (tid < o) sdata[tid] = fmaxf(sdata[tid], sdata[tid + o]);
        __syncthreads();
    }
    m = sdata[0];
    __syncthreads();

    float sum = 0.f;
    for (int s = tid; s < SS; s += 256) {
        float e = expf(row[s] - m);
        row[s] = e;
        sum += e;
    }
    sdata[tid] = sum;
    __syncthreads();
    for (int o = 128; o > 0; o >>= 1) {
        if (tid < o) sdata[tid] += sdata[tid + o];
        __syncthreads();
    }
    float inv = 1.f / sdata[0];
    for (int s = tid; s < SS; s += 256) w[(size_t)b * SS + s] = row[s] * inv;
}

// ---------------------------------------------------------------------------
// Kernel 4: context partials (S split 8 ways) + reduce
// ---------------------------------------------------------------------------
__global__ void __launch_bounds__(256) context_part_kernel(const float* __restrict__ values,
                                                           const float* __restrict__ w) {
    int b = blockIdx.x;
    int split = blockIdx.y;
    int s0 = split * 256;
    __shared__ float ws[256];
    ws[threadIdx.x] = w[(size_t)b * SS + s0 + threadIdx.x];
    __syncthreads();
    int d4 = threadIdx.x * 4;
    const float* vb = values + (size_t)b * SS * DD + (size_t)s0 * DD + d4;
    float4 acc = make_float4(0.f, 0.f, 0.f, 0.f);
    #pragma unroll 4
    for (int s = 0; s < 256; s++) {
        float wv = ws[s];
        float4 x = *reinterpret_cast<const float4*>(vb + (size_t)s * DD);
        acc.x += wv * x.x; acc.y += wv * x.y; acc.z += wv * x.z; acc.w += wv * x.w;
    }
    *reinterpret_cast<float4*>(g_ctx_part + ((size_t)split * BB + b) * DD + d4) = acc;
}

__global__ void __launch_bounds__(256) context_reduce_kernel(float* __restrict__ ctx) {
    int b = blockIdx.x;
    int d4 = threadIdx.x * 4;
    float4 acc = make_float4(0.f, 0.f, 0.f, 0.f);
    #pragma unroll
    for (int sp = 0; sp < 8; sp++) {
        float4 x = *reinterpret_cast<const float4*>(g_ctx_part + ((size_t)sp * BB + b) * DD + d4);
        acc.x += x.x; acc.y += x.y; acc.z += x.z; acc.w += x.w;
    }
    *reinterpret_cast<float4*>(ctx + (size_t)b * DD + d4) = acc;
}

// ---------------------------------------------------------------------------
// launch: inputs: query, values, W1, W2, v
// output: [context (B*D) | attention_weights (B*S)]
// ---------------------------------------------------------------------------
extern "C" void kernel_launch(void* const* d_in, const int* in_sizes, int n_in,
                              void* d_out, int out_size) {
    const float* query = (const float*)d_in[0];
    const float* values = (const float*)d_in[1];
    const float* W1 = (const float*)d_in[2];
    const float* W2 = (const float*)d_in[3];
    const float* v = (const float*)d_in[4];

    float* ctx = (float*)d_out;                 // [B, D]
    float* weights = (float*)d_out + BB * DD;   // [B, S]

    cudaFuncSetAttribute(scores_hmma_kernel,
                         cudaFuncAttributeMaxDynamicSharedMemorySize, SMEM_TOTAL);

    split_values_kernel<<<16384, 256>>>(values);
    split_w1t_kernel<<<dim3(DD / 64, HH / 64), 256>>>(W1);
    qp_kernel<<<dim3(BB, HH / 256), 256>>>(query, W2);
    scores_hmma_kernel<<<dim3(4, 512), 512, SMEM_TOTAL>>>(v);
    softmax_kernel<<<BB, 256>>>(weights);
    context_part_kernel<<<dim3(BB, 8), 256>>>(values, weights);
    context_reduce_kernel<<<BB, 256>>>(ctx);
}

// round 15
// speedup vs baseline: 4.2901x; 1.3518x over previous
#include <cuda_runtime.h>
#include <cuda_fp16.h>
#include <math.h>
#include <stdint.h>

#define BB 32
#define SS 2048
#define DD 1024
#define HH 1024
#define BS (BB * SS)
#define HD (HH * DD)

// ---------------- device scratch ----------------
__device__ __half g_Vhi[(size_t)BB * SS * DD];   // 128 MB (values in fp16, RN)
__device__ __half g_W[2 * (size_t)HD];           // 4 MB: [0,HD) = W1T hi, [HD,2HD) = W1T lo
__device__ float g_qp[BB * HH];
__device__ float g_scores_part[4 * BS];          // 1 MB
__device__ float g_ctx_part[8 * BB * DD];        // 1 MB

// ---------------- PTX helpers (baseline ISA, sm_80+) ----------------
__device__ __forceinline__ uint32_t smem_u32(const void* p) {
    uint32_t a;
    asm("{ .reg .u64 t; cvta.to.shared.u64 t, %1; cvt.u32.u64 %0, t; }" : "=r"(a) : "l"(p));
    return a;
}
#define CP_ASYNC16(dst, src) \
    asm volatile("cp.async.cg.shared.global [%0], [%1], 16;" :: "r"((uint32_t)(dst)), "l"(src) : "memory")
#define CP_A16I(dst, DIMM, src, SIMM) \
    asm volatile("cp.async.cg.shared.global [%0+%1], [%2+%3], 16;" \
                 :: "r"((uint32_t)(dst)), "n"(DIMM), "l"(src), "n"(SIMM) : "memory")
#define CP_COMMIT() asm volatile("cp.async.commit_group;" ::: "memory")
#define CP_WAIT1()  asm volatile("cp.async.wait_group 1;" ::: "memory")
#define CP_WAIT0()  asm volatile("cp.async.wait_group 0;" ::: "memory")

#define LDMX4I(r, base, IMM) \
    asm volatile("ldmatrix.sync.aligned.m8n8.x4.shared.b16 {%0,%1,%2,%3}, [%4+%5];" \
                 : "=r"((r)[0]), "=r"((r)[1]), "=r"((r)[2]), "=r"((r)[3]) \
                 : "r"(base), "n"(IMM))

__device__ __forceinline__ void mma16816(float* c, const uint32_t* a, const uint32_t* b) {
    asm volatile("mma.sync.aligned.m16n8k16.row.col.f32.f16.f16.f32 "
                 "{%0,%1,%2,%3}, {%4,%5,%6,%7}, {%8,%9}, {%0,%1,%2,%3};"
                 : "+f"(c[0]), "+f"(c[1]), "+f"(c[2]), "+f"(c[3])
                 : "r"(a[0]), "r"(a[1]), "r"(a[2]), "r"(a[3]), "r"(b[0]), "r"(b[1]));
}

// Fast accurate tanh: 2 MUFU + few ALU, abs err ~3e-6
__device__ __forceinline__ float tanh_fast(float x) {
    float xc = fminf(fmaxf(x, -20.f), 20.f);
    float t = __expf(2.f * xc);
    return 1.f - __fdividef(2.f, t + 1.f);
}

// smem layout (bytes). Rows padded to 80 B -> conflict-free ldmatrix.
#define ROWB    80
#define A_BUF   (128 * ROWB)      // 10240
#define B_BUF   (256 * ROWB)      // 20480
#define A_HI    0
#define B_HI    (A_BUF)           // 10240
#define B_LO    (A_BUF + B_BUF)   // 30720
#define STG_SZ  (A_BUF + 2 * B_BUF)       // 51200
#define QP_OFF  (3 * STG_SZ)              // 153600
#define VV_OFF  (QP_OFF + 1024)
#define RED_OFF (VV_OFF + 1024)
#define SMEM_TOTAL (RED_OFF + 2048)       // 157696

// ---------------------------------------------------------------------------
// Kernel 0a: values -> fp16 (hi only)
// ---------------------------------------------------------------------------
__global__ void __launch_bounds__(256) split_values_kernel(const float* __restrict__ values) {
    size_t base = (size_t)blockIdx.x * 4096;
    #pragma unroll
    for (int i = 0; i < 4; i++) {
        size_t g = base + (size_t)(i * 256 + threadIdx.x) * 4;
        float4 x = *reinterpret_cast<const float4*>(values + g);
        __half2 h01 = __half2(__float2half_rn(x.x), __float2half_rn(x.y));
        __half2 h23 = __half2(__float2half_rn(x.z), __float2half_rn(x.w));
        *reinterpret_cast<__half2*>(g_Vhi + g)     = h01;
        *reinterpret_cast<__half2*>(g_Vhi + g + 2) = h23;
    }
}

// ---------------------------------------------------------------------------
// Kernel 0b: W1[d][h] -> W1T[h][d] split into fp16 hi/lo (64x64 tiles)
// ---------------------------------------------------------------------------
__global__ void __launch_bounds__(256) split_w1t_kernel(const float* __restrict__ W1) {
    __shared__ float tile[64][65];
    int d0 = blockIdx.x * 64, h0 = blockIdx.y * 64;
    int r0 = threadIdx.x >> 6;
    int c = threadIdx.x & 63;
    #pragma unroll
    for (int i = 0; i < 16; i++) {
        int row = i * 4 + r0;
        tile[row][c] = W1[(size_t)(d0 + row) * HH + h0 + c];
    }
    __syncthreads();
    #pragma unroll
    for (int i = 0; i < 16; i++) {
        int hrow = i * 4 + r0;
        float x = tile[c][hrow];
        __half hi = __float2half_rn(x);
        __half lo = __float2half_rn(x - __half2float(hi));
        size_t o = (size_t)(h0 + hrow) * DD + d0 + c;
        g_W[o] = hi;
        g_W[HD + o] = lo;
    }
}

// ---------------------------------------------------------------------------
// Kernel 1: query_proj (fp32, tiny)
// ---------------------------------------------------------------------------
__global__ void __launch_bounds__(256) qp_kernel(const float* __restrict__ query,
                                                 const float* __restrict__ W2) {
    int b = blockIdx.x;
    int h = blockIdx.y * 256 + threadIdx.x;
    __shared__ float qs[DD];
    for (int d = threadIdx.x; d < DD; d += 256) qs[d] = query[b * DD + d];
    __syncthreads();
    float a0 = 0.f, a1 = 0.f, a2 = 0.f, a3 = 0.f;
    #pragma unroll 4
    for (int d = 0; d < DD; d += 4) {
        a0 += qs[d + 0] * W2[(size_t)(d + 0) * HH + h];
        a1 += qs[d + 1] * W2[(size_t)(d + 1) * HH + h];
        a2 += qs[d + 2] * W2[(size_t)(d + 2) * HH + h];
        a3 += qs[d + 3] * W2[(size_t)(d + 3) * HH + h];
    }
    g_qp[b * HH + h] = (a0 + a1) + (a2 + a3);
}

// ---------------------------------------------------------------------------
// Kernel 2: scores via 2-MMA fp16-split HMMA (A = fp16(values), B = hi+lo).
// grid(4 h-tiles, 512 m-tiles), 512 thr = 16 warps (4m x 4n),
// block tile 128x256, warp tile 32x64, 3-stage pipeline
// (wait -> barrier -> compute -> load). 64 MMAs per warp-chunk.
// ---------------------------------------------------------------------------

// one K=16 slice: KO = 0 or 32 bytes
template<int KO>
__device__ __forceinline__ void compute_ks(uint32_t aaddr, uint32_t baddr,
                                           float c[2][8][4]) {
    uint32_t ahi[2][4], q[4];
    uint32_t bhi[8][2], blo[8][2];

    // A + B hi loads
    LDMX4I(ahi[0], aaddr, KO);
    LDMX4I(ahi[1], aaddr, 1280 + KO);
    LDMX4I(q, baddr, KO);
    bhi[0][0] = q[0]; bhi[1][0] = q[1]; bhi[0][1] = q[2]; bhi[1][1] = q[3];
    LDMX4I(q, baddr, 1280 + KO);
    bhi[2][0] = q[0]; bhi[3][0] = q[1]; bhi[2][1] = q[2]; bhi[3][1] = q[3];
    LDMX4I(q, baddr, 2560 + KO);
    bhi[4][0] = q[0]; bhi[5][0] = q[1]; bhi[4][1] = q[2]; bhi[5][1] = q[3];
    LDMX4I(q, baddr, 3840 + KO);
    bhi[6][0] = q[0]; bhi[7][0] = q[1]; bhi[6][1] = q[2]; bhi[7][1] = q[3];

    // 8 MMAs a*bhi (mb=0) — covers blo LDSM latency below
    #pragma unroll
    for (int nb = 0; nb < 8; nb++) mma16816(c[0][nb], ahi[0], bhi[nb]);

    // B lo loads
    LDMX4I(q, baddr, 20480 + KO);
    blo[0][0] = q[0]; blo[1][0] = q[1]; blo[0][1] = q[2]; blo[1][1] = q[3];
    LDMX4I(q, baddr, 20480 + 1280 + KO);
    blo[2][0] = q[0]; blo[3][0] = q[1]; blo[2][1] = q[2]; blo[3][1] = q[3];
    LDMX4I(q, baddr, 20480 + 2560 + KO);
    blo[4][0] = q[0]; blo[5][0] = q[1]; blo[4][1] = q[2]; blo[5][1] = q[3];
    LDMX4I(q, baddr, 20480 + 3840 + KO);
    blo[6][0] = q[0]; blo[7][0] = q[1]; blo[6][1] = q[2]; blo[7][1] = q[3];

    // 8 MMAs a*bhi (mb=1)
    #pragma unroll
    for (int nb = 0; nb < 8; nb++) mma16816(c[1][nb], ahi[1], bhi[nb]);

    // 16 MMAs a*blo
    #pragma unroll
    for (int mb = 0; mb < 2; mb++)
        #pragma unroll
        for (int nb = 0; nb < 8; nb++) mma16816(c[mb][nb], ahi[mb], blo[nb]);
}

__global__ void __launch_bounds__(512, 1) scores_hmma_kernel(const float* __restrict__ vvec) {
    extern __shared__ __align__(16) char smem[];
    const uint32_t sb = smem_u32(smem);
    const int tid = threadIdx.x;
    const int wid = tid >> 5;
    const int lane = tid & 31;
    const int wm = wid >> 2;          // 0..3 (m)
    const int wn = wid & 3;           // 0..3 (n)
    const int m_w = wm * 32;
    const int n_w = wn * 64;

    const int h0 = blockIdx.x * 256;
    const int m0 = blockIdx.y * 128;
    const int b = m0 / SS;

    float* qp_sh = reinterpret_cast<float*>(smem + QP_OFF);
    float* v_sh  = reinterpret_cast<float*>(smem + VV_OFF);
    float* red   = reinterpret_cast<float*>(smem + RED_OFF);
    if (tid < 256) {
        qp_sh[tid] = g_qp[b * HH + h0 + tid];
        v_sh[tid]  = vvec[h0 + tid];
    }

    // ---- per-thread load pointers ----
    const int lrow = tid >> 2;        // 0..127
    const int lseg = tid & 3;         // 0..3
    const uint32_t a_off = (uint32_t)(lrow * ROWB + lseg * 16);
    const __half* pAhi = g_Vhi + (size_t)(m0 + lrow) * DD + lseg * 8;
    const __half* pW   = g_W   + (size_t)(h0 + lrow) * DD + lseg * 8;

    // ---- ldmatrix stage-relative base offsets ----
    const int l15 = lane & 15;
    const int lhi = lane >> 4;
    const uint32_t a_base0 = (uint32_t)(A_HI + (m_w + l15) * ROWB + lhi * 16);
    const uint32_t b_base0 = (uint32_t)(B_HI + (n_w + l15) * ROWB + lhi * 16);

    float c[2][8][4];
    #pragma unroll
    for (int mb = 0; mb < 2; mb++)
        #pragma unroll
        for (int nb = 0; nb < 8; nb++)
            #pragma unroll
            for (int r = 0; r < 4; r++) c[mb][nb][r] = 0.f;

    // ---- prologue: fill stages 0 and 1 ----
    #pragma unroll
    for (int p = 0; p < 2; p++) {
        uint32_t dst = sb + p * STG_SZ + a_off;
        int adv = p * 32;
        CP_ASYNC16(dst + 0,     pAhi + adv);
        CP_ASYNC16(dst + 10240, pW + adv);                 // B hi row lrow
        CP_ASYNC16(dst + 20480, pW + adv + 128 * DD);      // B hi row lrow+128
        CP_ASYNC16(dst + 30720, pW + adv + HD);            // B lo row lrow
        CP_ASYNC16(dst + 40960, pW + adv + HD + 128 * DD); // B lo row lrow+128
        CP_COMMIT();
    }
    pAhi += 64; pW += 64;

    uint32_t stg_cur = sb;                     // stage ch%3
    uint32_t stg_nxt = sb + 2 * STG_SZ;        // stage (ch+2)%3
    const uint32_t stg_hi = sb + 2 * STG_SZ;
    const int kfirst = (wid & 1);              // warp-parity ks stagger

    for (int ch = 0; ch < 32; ch++) {
        // own-group wait THEN barrier: chunk-ch data from all warps visible,
        // and stage stg_nxt (last read by all at ch-1) is free for refill.
        if (ch == 31) { CP_WAIT0(); } else { CP_WAIT1(); }
        __syncthreads();

        const uint32_t aaddr = stg_cur + a_base0;
        const uint32_t baddr = stg_cur + b_base0;
        if (kfirst) { compute_ks<32>(aaddr, baddr, c); compute_ks<0>(aaddr, baddr, c); }
        else        { compute_ks<0>(aaddr, baddr, c);  compute_ks<32>(aaddr, baddr, c); }

        // ---- issue loads for chunk ch+2 into stg_nxt ----
        if (ch + 2 < 32) {
            uint32_t dst = stg_nxt + a_off;
            CP_A16I(dst, 0,     pAhi, 0);
            CP_A16I(dst, 10240, pW, 0);
            CP_A16I(dst, 20480, pW, 128 * DD * 2);            // +262144 B
            CP_A16I(dst, 30720, pW, HD * 2);                  // +2097152 B
            CP_A16I(dst, 40960, pW, HD * 2 + 128 * DD * 2);   // +2359296 B
            CP_COMMIT();
            pAhi += 32; pW += 32;
        }
        stg_cur = (stg_cur == stg_hi) ? sb : (stg_cur + STG_SZ);
        stg_nxt = (stg_nxt == stg_hi) ? sb : (stg_nxt + STG_SZ);
    }

    // ---- epilogue: score partial = sum_h v[h]*tanh(c + qp[h]) ----
    float racc[2][2] = {{0.f, 0.f}, {0.f, 0.f}};
    #pragma unroll
    for (int mb = 0; mb < 2; mb++)
        #pragma unroll
        for (int nb = 0; nb < 8; nb++) {
            int colb = n_w + nb * 8 + 2 * (lane & 3);
            float q0 = qp_sh[colb], q1 = qp_sh[colb + 1];
            float v0 = v_sh[colb], v1 = v_sh[colb + 1];
            racc[mb][0] += v0 * tanh_fast(c[mb][nb][0] + q0) + v1 * tanh_fast(c[mb][nb][1] + q1);
            racc[mb][1] += v0 * tanh_fast(c[mb][nb][2] + q0) + v1 * tanh_fast(c[mb][nb][3] + q1);
        }
    #pragma unroll
    for (int off = 1; off <= 2; off <<= 1) {
        #pragma unroll
        for (int mb = 0; mb < 2; mb++) {
            racc[mb][0] += __shfl_xor_sync(0xffffffffu, racc[mb][0], off);
            racc[mb][1] += __shfl_xor_sync(0xffffffffu, racc[mb][1], off);
        }
    }
    __syncthreads();
    if ((lane & 3) == 0) {
        int g = lane >> 2;
        #pragma unroll
        for (int mb = 0; mb < 2; mb++) {
            red[(m_w + mb * 16 + g) * 4 + wn] = racc[mb][0];
            red[(m_w + mb * 16 + g + 8) * 4 + wn] = racc[mb][1];
        }
    }
    __syncthreads();
    if (tid < 128)
        g_scores_part[(size_t)blockIdx.x * BS + m0 + tid] =
            (red[tid * 4] + red[tid * 4 + 1]) + (red[tid * 4 + 2] + red[tid * 4 + 3]);
}

// ---------------------------------------------------------------------------
// Kernel 3: sum 4 partials + softmax over S per batch row
// ---------------------------------------------------------------------------
__global__ void __launch_bounds__(256) softmax_kernel(float* __restrict__ w) {
    int b = blockIdx.x;
    __shared__ float row[SS];
    __shared__ float sdata[256];
    int tid = threadIdx.x;

    for (int s = tid; s < SS; s += 256) {
        float acc = 0.f;
        #pragma unroll
        for (int p = 0; p < 4; p++) acc += g_scores_part[(size_t)p * BS + b * SS + s];
        row[s] = acc;
    }
    __syncthreads();

    float m = -INFINITY;
    for (int s = tid; s < SS; s += 256) m = fmaxf(m, row[s]);
    sdata[tid] = m;
    __syncthreads();
    for (int o = 128; o > 0; o >>= 1) {
        if (tid < o) sdata[tid] = fmaxf(sdata[tid], sdata[tid + o]);
        __syncthreads();
    }
    m = sdata[0];
    __syncthreads();

    float sum = 0.f;
    for (int s = tid; s < SS; s += 256) {
        float e = expf(row[s] - m);
        row[s] = e;
        sum += e;
    }
    sdata[tid] = sum;
    __syncthreads();
    for (int o = 128; o > 0; o >>= 1) {
        if (tid < o) sdata[tid] += sdata[tid + o];
        __syncthreads();
    }
    float inv = 1.f / sdata[0];
    for (int s = tid; s < SS; s += 256) w[(size_t)b * SS + s] = row[s] * inv;
}

// ---------------------------------------------------------------------------
// Kernel 4: context partials (S split 8 ways) + reduce
// ---------------------------------------------------------------------------
__global__ void __launch_bounds__(256) context_part_kernel(const float* __restrict__ values,
                                                           const float* __restrict__ w) {
    int b = blockIdx.x;
    int split = blockIdx.y;
    int s0 = split * 256;
    __shared__ float ws[256];
    ws[threadIdx.x] = w[(size_t)b * SS + s0 + threadIdx.x];
    __syncthreads();
    int d4 = threadIdx.x * 4;
    const float* vb = values + (size_t)b * SS * DD + (size_t)s0 * DD + d4;
    float4 acc = make_float4(0.f, 0.f, 0.f, 0.f);
    #pragma unroll 4
    for (int s = 0; s < 256; s++) {
        float wv = ws[s];
        float4 x = *reinterpret_cast<const float4*>(vb + (size_t)s * DD);
        acc.x += wv * x.x; acc.y += wv * x.y; acc.z += wv * x.z; acc.w += wv * x.w;
    }
    *reinterpret_cast<float4*>(g_ctx_part + ((size_t)split * BB + b) * DD + d4) = acc;
}

__global__ void __launch_bounds__(256) context_reduce_kernel(float* __restrict__ ctx) {
    int b = blockIdx.x;
    int d4 = threadIdx.x * 4;
    float4 acc = make_float4(0.f, 0.f, 0.f, 0.f);
    #pragma unroll
    for (int sp = 0; sp < 8; sp++) {
        float4 x = *reinterpret_cast<const float4*>(g_ctx_part + ((size_t)sp * BB + b) * DD + d4);
        acc.x += x.x; acc.y += x.y; acc.z += x.z; acc.w += x.w;
    }
    *reinterpret_cast<float4*>(ctx + (size_t)b * DD + d4) = acc;
}

// ---------------------------------------------------------------------------
// launch: inputs: query, values, W1, W2, v
// output: [context (B*D) | attention_weights (B*S)]
// ---------------------------------------------------------------------------
extern "C" void kernel_launch(void* const* d_in, const int* in_sizes, int n_in,
                              void* d_out, int out_size) {
    const float* query = (const float*)d_in[0];
    const float* values = (const float*)d_in[1];
    const float* W1 = (const float*)d_in[2];
    const float* W2 = (const float*)d_in[3];
    const float* v = (const float*)d_in[4];

    float* ctx = (float*)d_out;                 // [B, D]
    float* weights = (float*)d_out + BB * DD;   // [B, S]

    cudaFuncSetAttribute(scores_hmma_kernel,
                         cudaFuncAttributeMaxDynamicSharedMemorySize, SMEM_TOTAL);

    split_values_kernel<<<16384, 256>>>(values);
    split_w1t_kernel<<<dim3(DD / 64, HH / 64), 256>>>(W1);
    qp_kernel<<<dim3(BB, HH / 256), 256>>>(query, W2);
    scores_hmma_kernel<<<dim3(4, 512), 512, SMEM_TOTAL>>>(v);
    softmax_kernel<<<BB, 256>>>(weights);
    context_part_kernel<<<dim3(BB, 8), 256>>>(values, weights);
    context_reduce_kernel<<<BB, 256>>>(ctx);
}

// round 16
// speedup vs baseline: 4.8036x; 1.1197x over previous
#include <cuda_runtime.h>
#include <cuda_fp16.h>
#include <math.h>
#include <stdint.h>

#define BB 32
#define SS 2048
#define DD 1024
#define HH 1024
#define BS (BB * SS)
#define HD (HH * DD)

// ---------------- device scratch ----------------
__device__ __half g_Vhi[(size_t)BB * SS * DD];   // 128 MB (values in fp16, RN)
__device__ __half g_W[2 * (size_t)HD];           // 4 MB: [0,HD) = W1T hi, [HD,2HD) = W1T lo
__device__ float g_qp[BB * HH];
__device__ float g_scores_part[8 * BS];          // 2 MB
__device__ float g_ctx_part[16 * BB * DD];       // 2 MB

// ---------------- PTX helpers (baseline ISA, sm_80+) ----------------
__device__ __forceinline__ uint32_t smem_u32(const void* p) {
    uint32_t a;
    asm("{ .reg .u64 t; cvta.to.shared.u64 t, %1; cvt.u32.u64 %0, t; }" : "=r"(a) : "l"(p));
    return a;
}
#define CP_ASYNC16(dst, src) \
    asm volatile("cp.async.cg.shared.global [%0], [%1], 16;" :: "r"((uint32_t)(dst)), "l"(src) : "memory")
#define CP_A16I(dst, DIMM, src, SIMM) \
    asm volatile("cp.async.cg.shared.global [%0+%1], [%2+%3], 16;" \
                 :: "r"((uint32_t)(dst)), "n"(DIMM), "l"(src), "n"(SIMM) : "memory")
#define CP_COMMIT() asm volatile("cp.async.commit_group;" ::: "memory")
#define CP_WAIT1()  asm volatile("cp.async.wait_group 1;" ::: "memory")
#define CP_WAIT0()  asm volatile("cp.async.wait_group 0;" ::: "memory")

#define LDMX4I(r, base, IMM) \
    asm volatile("ldmatrix.sync.aligned.m8n8.x4.shared.b16 {%0,%1,%2,%3}, [%4+%5];" \
                 : "=r"((r)[0]), "=r"((r)[1]), "=r"((r)[2]), "=r"((r)[3]) \
                 : "r"(base), "n"(IMM))

__device__ __forceinline__ void mma16816(float* c, const uint32_t* a, const uint32_t* b) {
    asm volatile("mma.sync.aligned.m16n8k16.row.col.f32.f16.f16.f32 "
                 "{%0,%1,%2,%3}, {%4,%5,%6,%7}, {%8,%9}, {%0,%1,%2,%3};"
                 : "+f"(c[0]), "+f"(c[1]), "+f"(c[2]), "+f"(c[3])
                 : "r"(a[0]), "r"(a[1]), "r"(a[2]), "r"(a[3]), "r"(b[0]), "r"(b[1]));
}

// Fast accurate tanh: 2 MUFU + few ALU, abs err ~3e-6
__device__ __forceinline__ float tanh_fast(float x) {
    float xc = fminf(fmaxf(x, -20.f), 20.f);
    float t = __expf(2.f * xc);
    return 1.f - __fdividef(2.f, t + 1.f);
}

// smem layout (bytes). Rows padded to 80 B -> conflict-free ldmatrix.
// Tile 128x128: A(128 rows) + Bhi(128 rows) + Blo(128 rows).
#define ROWB    80
#define A_BUF   (128 * ROWB)      // 10240
#define A_HI    0
#define B_HI    (A_BUF)           // 10240
#define B_LO    (2 * A_BUF)       // 20480
#define STG_SZ  (3 * A_BUF)       // 30720
#define QP_OFF  (3 * STG_SZ)      // 92160
#define VV_OFF  (QP_OFF + 512)
#define RED_OFF (VV_OFF + 512)
#define SMEM_TOTAL (RED_OFF + 1024)   // 94208  (x2 blocks/SM = 188416)

// ---------------------------------------------------------------------------
// Kernel 0a: values -> fp16 (hi only)
// ---------------------------------------------------------------------------
__global__ void __launch_bounds__(256) split_values_kernel(const float* __restrict__ values) {
    size_t base = (size_t)blockIdx.x * 4096;
    #pragma unroll
    for (int i = 0; i < 4; i++) {
        size_t g = base + (size_t)(i * 256 + threadIdx.x) * 4;
        float4 x = *reinterpret_cast<const float4*>(values + g);
        __half2 h01 = __half2(__float2half_rn(x.x), __float2half_rn(x.y));
        __half2 h23 = __half2(__float2half_rn(x.z), __float2half_rn(x.w));
        *reinterpret_cast<__half2*>(g_Vhi + g)     = h01;
        *reinterpret_cast<__half2*>(g_Vhi + g + 2) = h23;
    }
}

// ---------------------------------------------------------------------------
// Kernel 0b: W1[d][h] -> W1T[h][d] split into fp16 hi/lo (64x64 tiles)
// ---------------------------------------------------------------------------
__global__ void __launch_bounds__(256) split_w1t_kernel(const float* __restrict__ W1) {
    __shared__ float tile[64][65];
    int d0 = blockIdx.x * 64, h0 = blockIdx.y * 64;
    int r0 = threadIdx.x >> 6;
    int c = threadIdx.x & 63;
    #pragma unroll
    for (int i = 0; i < 16; i++) {
        int row = i * 4 + r0;
        tile[row][c] = W1[(size_t)(d0 + row) * HH + h0 + c];
    }
    __syncthreads();
    #pragma unroll
    for (int i = 0; i < 16; i++) {
        int hrow = i * 4 + r0;
        float x = tile[c][hrow];
        __half hi = __float2half_rn(x);
        __half lo = __float2half_rn(x - __half2float(hi));
        size_t o = (size_t)(h0 + hrow) * DD + d0 + c;
        g_W[o] = hi;
        g_W[HD + o] = lo;
    }
}

// ---------------------------------------------------------------------------
// Kernel 1: query_proj (fp32, tiny)
// ---------------------------------------------------------------------------
__global__ void __launch_bounds__(256) qp_kernel(const float* __restrict__ query,
                                                 const float* __restrict__ W2) {
    int b = blockIdx.x;
    int h = blockIdx.y * 256 + threadIdx.x;
    __shared__ float qs[DD];
    for (int d = threadIdx.x; d < DD; d += 256) qs[d] = query[b * DD + d];
    __syncthreads();
    float a0 = 0.f, a1 = 0.f, a2 = 0.f, a3 = 0.f;
    #pragma unroll 4
    for (int d = 0; d < DD; d += 4) {
        a0 += qs[d + 0] * W2[(size_t)(d + 0) * HH + h];
        a1 += qs[d + 1] * W2[(size_t)(d + 1) * HH + h];
        a2 += qs[d + 2] * W2[(size_t)(d + 2) * HH + h];
        a3 += qs[d + 3] * W2[(size_t)(d + 3) * HH + h];
    }
    g_qp[b * HH + h] = (a0 + a1) + (a2 + a3);
}

// ---------------------------------------------------------------------------
// Kernel 2: scores via 2-MMA fp16-split HMMA (A = fp16(values), B = hi+lo).
// grid(8 h-tiles, 512 m-tiles), 256 thr = 8 warps (4m x 2n),
// block tile 128x128, warp tile 32x64. TWO blocks co-resident per SM
// (independent barrier domains -> de-phased pipelines). 3-stage pipeline
// (wait -> barrier -> compute -> load).
// ---------------------------------------------------------------------------

// one K=16 slice: KO = 0 or 32 bytes
template<int KO>
__device__ __forceinline__ void compute_ks(uint32_t aaddr, uint32_t baddr,
                                           float c[2][8][4]) {
    uint32_t ahi[2][4], q[4];
    uint32_t bhi[8][2], blo[8][2];

    // A + B hi loads
    LDMX4I(ahi[0], aaddr, KO);
    LDMX4I(ahi[1], aaddr, 1280 + KO);
    LDMX4I(q, baddr, KO);
    bhi[0][0] = q[0]; bhi[1][0] = q[1]; bhi[0][1] = q[2]; bhi[1][1] = q[3];
    LDMX4I(q, baddr, 1280 + KO);
    bhi[2][0] = q[0]; bhi[3][0] = q[1]; bhi[2][1] = q[2]; bhi[3][1] = q[3];
    LDMX4I(q, baddr, 2560 + KO);
    bhi[4][0] = q[0]; bhi[5][0] = q[1]; bhi[4][1] = q[2]; bhi[5][1] = q[3];
    LDMX4I(q, baddr, 3840 + KO);
    bhi[6][0] = q[0]; bhi[7][0] = q[1]; bhi[6][1] = q[2]; bhi[7][1] = q[3];

    // 8 MMAs a*bhi (mb=0) — covers blo LDSM latency below
    #pragma unroll
    for (int nb = 0; nb < 8; nb++) mma16816(c[0][nb], ahi[0], bhi[nb]);

    // B lo loads (B_LO - B_HI = 10240)
    LDMX4I(q, baddr, 10240 + KO);
    blo[0][0] = q[0]; blo[1][0] = q[1]; blo[0][1] = q[2]; blo[1][1] = q[3];
    LDMX4I(q, baddr, 10240 + 1280 + KO);
    blo[2][0] = q[0]; blo[3][0] = q[1]; blo[2][1] = q[2]; blo[3][1] = q[3];
    LDMX4I(q, baddr, 10240 + 2560 + KO);
    blo[4][0] = q[0]; blo[5][0] = q[1]; blo[4][1] = q[2]; blo[5][1] = q[3];
    LDMX4I(q, baddr, 10240 + 3840 + KO);
    blo[6][0] = q[0]; blo[7][0] = q[1]; blo[6][1] = q[2]; blo[7][1] = q[3];

    // 8 MMAs a*bhi (mb=1)
    #pragma unroll
    for (int nb = 0; nb < 8; nb++) mma16816(c[1][nb], ahi[1], bhi[nb]);

    // 16 MMAs a*blo
    #pragma unroll
    for (int mb = 0; mb < 2; mb++)
        #pragma unroll
        for (int nb = 0; nb < 8; nb++) mma16816(c[mb][nb], ahi[mb], blo[nb]);
}

__global__ void __launch_bounds__(256, 2) scores_hmma_kernel(const float* __restrict__ vvec) {
    extern __shared__ __align__(16) char smem[];
    const uint32_t sb = smem_u32(smem);
    const int tid = threadIdx.x;
    const int wid = tid >> 5;
    const int lane = tid & 31;
    const int wm = wid >> 1;          // 0..3 (m)
    const int wn = wid & 1;           // 0..1 (n)
    const int m_w = wm * 32;
    const int n_w = wn * 64;

    const int h0 = blockIdx.x * 128;
    const int m0 = blockIdx.y * 128;
    const int b = m0 / SS;

    float* qp_sh = reinterpret_cast<float*>(smem + QP_OFF);
    float* v_sh  = reinterpret_cast<float*>(smem + VV_OFF);
    float* red   = reinterpret_cast<float*>(smem + RED_OFF);
    if (tid < 128) {
        qp_sh[tid] = g_qp[b * HH + h0 + tid];
        v_sh[tid]  = vvec[h0 + tid];
    }

    // ---- per-thread load pointers ----
    const int lrow = tid >> 2;        // 0..63
    const int lseg = tid & 3;         // 0..3
    const uint32_t a_off = (uint32_t)(lrow * ROWB + lseg * 16);
    const __half* pA0 = g_Vhi + (size_t)(m0 + lrow) * DD + lseg * 8;
    const __half* pA1 = pA0 + (size_t)64 * DD;
    const __half* pW0 = g_W   + (size_t)(h0 + lrow) * DD + lseg * 8;
    const __half* pW1 = pW0 + (size_t)64 * DD;

    // ---- ldmatrix stage-relative base offsets ----
    const int l15 = lane & 15;
    const int lhi = lane >> 4;
    const uint32_t a_base0 = (uint32_t)(A_HI + (m_w + l15) * ROWB + lhi * 16);
    const uint32_t b_base0 = (uint32_t)(B_HI + (n_w + l15) * ROWB + lhi * 16);

    float c[2][8][4];
    #pragma unroll
    for (int mb = 0; mb < 2; mb++)
        #pragma unroll
        for (int nb = 0; nb < 8; nb++)
            #pragma unroll
            for (int r = 0; r < 4; r++) c[mb][nb][r] = 0.f;

    // ---- prologue: fill stages 0 and 1 ----
    #pragma unroll
    for (int p = 0; p < 2; p++) {
        uint32_t dst = sb + p * STG_SZ + a_off;
        int adv = p * 32;
        CP_ASYNC16(dst + 0,           pA0 + adv);
        CP_ASYNC16(dst + 5120,        pA1 + adv);
        CP_ASYNC16(dst + 10240,       pW0 + adv);
        CP_ASYNC16(dst + 10240 + 5120, pW1 + adv);
        CP_ASYNC16(dst + 20480,       pW0 + adv + HD);
        CP_ASYNC16(dst + 20480 + 5120, pW1 + adv + HD);
        CP_COMMIT();
    }
    pA0 += 64; pA1 += 64; pW0 += 64; pW1 += 64;

    uint32_t stg_cur = sb;                     // stage ch%3
    uint32_t stg_nxt = sb + 2 * STG_SZ;        // stage (ch+2)%3
    const uint32_t stg_hi = sb + 2 * STG_SZ;
    const int kfirst = (wid >> 2) & 1;         // de-phase SMSP siblings

    for (int ch = 0; ch < 32; ch++) {
        // own-group wait THEN barrier: chunk-ch data from all warps visible,
        // and stage stg_nxt (last read by all at ch-1) is free for refill.
        if (ch == 31) { CP_WAIT0(); } else { CP_WAIT1(); }
        __syncthreads();

        const uint32_t aaddr = stg_cur + a_base0;
        const uint32_t baddr = stg_cur + b_base0;
        if (kfirst) { compute_ks<32>(aaddr, baddr, c); compute_ks<0>(aaddr, baddr, c); }
        else        { compute_ks<0>(aaddr, baddr, c);  compute_ks<32>(aaddr, baddr, c); }

        // ---- issue loads for chunk ch+2 into stg_nxt ----
        if (ch + 2 < 32) {
            uint32_t dst = stg_nxt + a_off;
            CP_A16I(dst, 0,     pA0, 0);
            CP_A16I(dst, 5120,  pA1, 0);
            CP_A16I(dst, 10240, pW0, 0);
            CP_A16I(dst, 15360, pW1, 0);
            CP_A16I(dst, 20480, pW0, HD * 2);   // +2097152 B  (W1T lo)
            CP_A16I(dst, 25600, pW1, HD * 2);
            CP_COMMIT();
            pA0 += 32; pA1 += 32; pW0 += 32; pW1 += 32;
        }
        stg_cur = (stg_cur == stg_hi) ? sb : (stg_cur + STG_SZ);
        stg_nxt = (stg_nxt == stg_hi) ? sb : (stg_nxt + STG_SZ);
    }

    // ---- epilogue: score partial = sum_h v[h]*tanh(c + qp[h]) ----
    float racc[2][2] = {{0.f, 0.f}, {0.f, 0.f}};
    #pragma unroll
    for (int mb = 0; mb < 2; mb++)
        #pragma unroll
        for (int nb = 0; nb < 8; nb++) {
            int colb = n_w + nb * 8 + 2 * (lane & 3);
            float q0 = qp_sh[colb], q1 = qp_sh[colb + 1];
            float v0 = v_sh[colb], v1 = v_sh[colb + 1];
            racc[mb][0] += v0 * tanh_fast(c[mb][nb][0] + q0) + v1 * tanh_fast(c[mb][nb][1] + q1);
            racc[mb][1] += v0 * tanh_fast(c[mb][nb][2] + q0) + v1 * tanh_fast(c[mb][nb][3] + q1);
        }
    #pragma unroll
    for (int off = 1; off <= 2; off <<= 1) {
        #pragma unroll
        for (int mb = 0; mb < 2; mb++) {
            racc[mb][0] += __shfl_xor_sync(0xffffffffu, racc[mb][0], off);
            racc[mb][1] += __shfl_xor_sync(0xffffffffu, racc[mb][1], off);
        }
    }
    __syncthreads();
    if ((lane & 3) == 0) {
        int g = lane >> 2;
        #pragma unroll
        for (int mb = 0; mb < 2; mb++) {
            red[(m_w + mb * 16 + g) * 2 + wn] = racc[mb][0];
            red[(m_w + mb * 16 + g + 8) * 2 + wn] = racc[mb][1];
        }
    }
    __syncthreads();
    if (tid < 128)
        g_scores_part[(size_t)blockIdx.x * BS + m0 + tid] =
            red[tid * 2] + red[tid * 2 + 1];
}

// ---------------------------------------------------------------------------
// Kernel 3: sum 8 partials + softmax over S per batch row
// ---------------------------------------------------------------------------
__global__ void __launch_bounds__(256) softmax_kernel(float* __restrict__ w) {
    int b = blockIdx.x;
    __shared__ float row[SS];
    __shared__ float sdata[256];
    int tid = threadIdx.x;

    for (int s = tid; s < SS; s += 256) {
        float acc = 0.f;
        #pragma unroll
        for (int p = 0; p < 8; p++) acc += g_scores_part[(size_t)p * BS + b * SS + s];
        row[s] = acc;
    }
    __syncthreads();

    float m = -INFINITY;
    for (int s = tid; s < SS; s += 256) m = fmaxf(m, row[s]);
    sdata[tid] = m;
    __syncthreads();
    for (int o = 128; o > 0; o >>= 1) {
        if (tid < o) sdata[tid] = fmaxf(sdata[tid], sdata[tid + o]);
        __syncthreads();
    }
    m = sdata[0];
    __syncthreads();

    float sum = 0.f;
    for (int s = tid; s < SS; s += 256) {
        float e = expf(row[s] - m);
        row[s] = e;
        sum += e;
    }
    sdata[tid] = sum;
    __syncthreads();
    for (int o = 128; o > 0; o >>= 1) {
        if (tid < o) sdata[tid] += sdata[tid + o];
        __syncthreads();
    }
    float inv = 1.f / sdata[0];
    for (int s = tid; s < SS; s += 256) w[(size_t)b * SS + s] = row[s] * inv;
}

// ---------------------------------------------------------------------------
// Kernel 4: context partials (S split 16 ways) + reduce
// ---------------------------------------------------------------------------
__global__ void __launch_bounds__(256) context_part_kernel(const float* __restrict__ values,
                                                           const float* __restrict__ w) {
    int b = blockIdx.x;
    int split = blockIdx.y;
    int s0 = split * 128;
    __shared__ float ws[128];
    if (threadIdx.x < 128) ws[threadIdx.x] = w[(size_t)b * SS + s0 + threadIdx.x];
    __syncthreads();
    int d4 = threadIdx.x * 4;
    const float* vb = values + (size_t)b * SS * DD + (size_t)s0 * DD + d4;
    float4 acc = make_float4(0.f, 0.f, 0.f, 0.f);
    #pragma unroll 8
    for (int s = 0; s < 128; s++) {
        float wv = ws[s];
        float4 x = *reinterpret_cast<const float4*>(vb + (size_t)s * DD);
        acc.x += wv * x.x; acc.y += wv * x.y; acc.z += wv * x.z; acc.w += wv * x.w;
    }
    *reinterpret_cast<float4*>(g_ctx_part + ((size_t)split * BB + b) * DD + d4) = acc;
}

__global__ void __launch_bounds__(256) context_reduce_kernel(float* __restrict__ ctx) {
    int b = blockIdx.x;
    int d4 = threadIdx.x * 4;
    float4 acc = make_float4(0.f, 0.f, 0.f, 0.f);
    #pragma unroll
    for (int sp = 0; sp < 16; sp++) {
        float4 x = *reinterpret_cast<const float4*>(g_ctx_part + ((size_t)sp * BB + b) * DD + d4);
        acc.x += x.x; acc.y += x.y; acc.z += x.z; acc.w += x.w;
    }
    *reinterpret_cast<float4*>(ctx + (size_t)b * DD + d4) = acc;
}

// ---------------------------------------------------------------------------
// launch: inputs: query, values, W1, W2, v
// output: [context (B*D) | attention_weights (B*S)]
// ---------------------------------------------------------------------------
extern "C" void kernel_launch(void* const* d_in, const int* in_sizes, int n_in,
                              void* d_out, int out_size) {
    const float* query = (const float*)d_in[0];
    const float* values = (const float*)d_in[1];
    const float* W1 = (const float*)d_in[2];
    const float* W2 = (const float*)d_in[3];
    const float* v = (const float*)d_in[4];

    float* ctx = (float*)d_out;                 // [B, D]
    float* weights = (float*)d_out + BB * DD;   // [B, S]

    cudaFuncSetAttribute(scores_hmma_kernel,
                         cudaFuncAttributeMaxDynamicSharedMemorySize, SMEM_TOTAL);

    split_values_kernel<<<16384, 256>>>(values);
    split_w1t_kernel<<<dim3(DD / 64, HH / 64), 256>>>(W1);
    qp_kernel<<<dim3(BB, HH / 256), 256>>>(query, W2);
    scores_hmma_kernel<<<dim3(8, 512), 256, SMEM_TOTAL>>>(v);
    softmax_kernel<<<BB, 256>>>(weights);
    context_part_kernel<<<dim3(BB, 16), 256>>>(values, weights);
    context_reduce_kernel<<<BB, 256>>>(ctx);
}